// round 13
// baseline (speedup 1.0000x reference)
#include <cuda_runtime.h>
#include <math.h>

#define H    224
#define W    224
#define HW   (224*224)
#define C    21
#define K    48
#define H2   67
#define W2   67
#define HW2  (67*67)
#define MH   56
#define MW   56
#define PAD  24
#define PW   272
#define PHW  (272*272)
#define EPSF 1e-8f
#define W1F  0.3f

// ---------------- device scratch ----------------
__device__ __align__(16) float g_pad0[C*PHW];
__device__ __align__(16) float g_pad1[C*PHW];
__device__ __align__(16) float g_imgp[3*PHW];
__device__ __align__(16) float g_aff [K*HW];     // K-MAJOR: [k][p]
__device__ __align__(16) float g_imgs2[3*HW2];
__device__ __align__(16) float g_aff2p[HW2*K];   // pixel-major [p2][k]

struct PosArr { float v[K]; };

__device__ __forceinline__ int clampi(int v, int lo, int hi) {
    return v < lo ? lo : (v > hi ? hi : v);
}

// ---------------- fused prep: upmask->pad0, padimg, downimg -------------------
__global__ void prep_kernel(const float* __restrict__ imgs,
                            const float* __restrict__ masks) {
    int idx = blockIdx.x * blockDim.x + threadIdx.x;
    if (idx < C*PHW) {
        int c = idx / PHW;
        int q = idx - c * PHW;
        int py = q / PW, px = q - py * PW;
        int y = clampi(py - PAD, 0, H-1);
        int x = clampi(px - PAD, 0, W-1);
        float fy = (float)y * (55.f / 223.f);
        int y0 = (int)fy; float wy = fy - (float)y0; int y1 = min(y0 + 1, 55);
        float fx = (float)x * (55.f / 223.f);
        int x0 = (int)fx; float wx = fx - (float)x0; int x1 = min(x0 + 1, 55);
        const float* mc = masks + c * MH * MW;
        float r0 = mc[y0*MW+x0] * (1.f - wy) + mc[y1*MW+x0] * wy;
        float r1 = mc[y0*MW+x1] * (1.f - wy) + mc[y1*MW+x1] * wy;
        g_pad0[idx] = r0 * (1.f - wx) + r1 * wx;
        return;
    }
    idx -= C*PHW;
    if (idx < 3*PHW) {
        int c = idx / PHW;
        int q = idx - c * PHW;
        int py = q / PW, px = q - py * PW;
        int y = clampi(py - PAD, 0, H-1);
        int x = clampi(px - PAD, 0, W-1);
        g_imgp[idx] = imgs[c*HW + y*W + x];
        return;
    }
    idx -= 3*PHW;
    if (idx < 3*HW2) {
        int c = idx / HW2;
        int p = idx - c * HW2;
        int y = p / W2, x = p - y * W2;
        float fy = (float)y * (223.f / 66.f);
        int y0 = (int)fy; float wy = fy - (float)y0; int y1 = min(y0 + 1, 223);
        float fx = (float)x * (223.f / 66.f);
        int x0 = (int)fx; float wx = fx - (float)x0; int x1 = min(x0 + 1, 223);
        const float* ic = imgs + c * HW;
        float r0 = ic[y0*W+x0] * (1.f - wy) + ic[y1*W+x0] * wy;
        float r1 = ic[y0*W+x1] * (1.f - wy) + ic[y1*W+x1] * wy;
        g_imgs2[idx] = r0 * (1.f - wx) + r1 * wx;
    }
}

#define NB_ADDR(o, DI) \
    ((o)==0 ? rm[DI]+cm[DI] : (o)==1 ? rm[DI]+x   : (o)==2 ? rm[DI]+cp[DI] : \
     (o)==3 ? r0v  +cm[DI] : (o)==4 ? r0v  +cp[DI] : \
     (o)==5 ? rp[DI]+cm[DI] : (o)==6 ? rp[DI]+x   :            rp[DI]+cp[DI])

// ---------------- low-res affinity, pixel-major out ---------------------------
__global__ __launch_bounds__(32) void aff2_kernel() {
    int p = blockIdx.x * blockDim.x + threadIdx.x;
    if (p >= HW2) return;
    int y = p / W2, x = p - y * W2;
    const int DDc[6] = {1, 2, 4, 8, 12, 24};
    int rm[6], rp[6], cm[6], cp[6];
    #pragma unroll
    for (int di = 0; di < 6; di++) {
        int d = DDc[di];
        rm[di] = max(y - d, 0) * W2;
        rp[di] = min(y + d, H2-1) * W2;
        cm[di] = max(x - d, 0);
        cp[di] = min(x + d, W2-1);
    }
    int r0v = y * W2;

    float t[K];
    #pragma unroll
    for (int k = 0; k < K; k++) t[k] = 0.f;

    for (int c = 0; c < 3; c++) {
        const float* __restrict__ im = g_imgs2 + c * HW2;
        float ctr = im[p];
        float sum = 0.f, ss = 0.f;
        #pragma unroll
        for (int di = 0; di < 6; di++) {
            #pragma unroll
            for (int o = 0; o < 8; o++) {
                float v = im[NB_ADDR(o, di)];
                sum += v; ss = fmaf(v, v, ss);
            }
        }
        float mean = sum * (1.f/48.f);
        float var  = fmaxf((ss - sum * mean) * (1.f/47.f), 0.f);
        float inv  = 1.f / (sqrtf(var) + EPSF);
        float inv2 = inv * inv;
        #pragma unroll
        for (int di = 0; di < 6; di++) {
            #pragma unroll
            for (int o = 0; o < 8; o++) {
                float d = im[NB_ADDR(o, di)] - ctr;
                t[di*8+o] = fmaf(d * d, inv2, t[di*8+o]);
            }
        }
    }
    #pragma unroll
    for (int k = 0; k < K; k++) g_aff2p[p*K + k] = -t[k] * (1.f/3.f);
}

// ------- fused: fullres affinity softmax + upsampled aff2 softmax + pos -------
__global__ __launch_bounds__(128) void aff1up_kernel(PosArr pos) {
    const int x = blockIdx.x * 32 + threadIdx.x;
    const int y = blockIdx.y * 4  + threadIdx.y;
    const int p = y * W + x;
    const int pp = (y + PAD) * PW + (x + PAD);

    const int DY[8] = {-1,-1,-1, 0, 0, 1, 1, 1};
    const int DX[8] = {-1, 0, 1,-1, 1,-1, 0, 1};
    const int DDc[6] = {1, 2, 4, 8, 12, 24};

    float t[K];
    #pragma unroll
    for (int k = 0; k < K; k++) t[k] = 0.f;

    #pragma unroll 1
    for (int c = 0; c < 3; c++) {
        const float* __restrict__ im = g_imgp + c * PHW + pp;
        float ctr = im[0];
        float sum = 0.f, ss = 0.f;
        #pragma unroll
        for (int di = 0; di < 6; di++) {
            #pragma unroll
            for (int o = 0; o < 8; o++) {
                float v = im[DY[o]*DDc[di]*PW + DX[o]*DDc[di]];
                sum += v; ss = fmaf(v, v, ss);
            }
        }
        float mean = sum * (1.f/48.f);
        float var  = fmaxf((ss - sum * mean) * (1.f/47.f), 0.f);
        float inv  = 1.f / ((sqrtf(var) + EPSF) * W1F);
        float inv2 = inv * inv;
        #pragma unroll
        for (int di = 0; di < 6; di++) {
            #pragma unroll
            for (int o = 0; o < 8; o++) {
                float d = im[DY[o]*DDc[di]*PW + DX[o]*DDc[di]] - ctr;
                t[di*8+o] = fmaf(d * d, inv2, t[di*8+o]);
            }
        }
    }
    {
        float mx = -1e30f;
        #pragma unroll
        for (int k = 0; k < K; k++) { t[k] = -t[k] * (1.f/3.f); mx = fmaxf(mx, t[k]); }
        float es = 0.f;
        #pragma unroll
        for (int k = 0; k < K; k++) { t[k] = __expf(t[k] - mx); es += t[k]; }
        float inv = 1.f / es;
        #pragma unroll
        for (int k = 0; k < K; k++) t[k] *= inv;
    }

    {
        float fy = (float)y * (66.f / 223.f);
        int iy = (int)fy; float wy = fy - (float)iy; int iy1 = min(iy + 1, 66);
        float fx = (float)x * (66.f / 223.f);
        int ix = (int)fx; float wx = fx - (float)ix; int ix1 = min(ix + 1, 66);
        float w00 = (1.f-wy)*(1.f-wx), w01 = (1.f-wy)*wx;
        float w10 = wy*(1.f-wx),       w11 = wy*wx;

        const float4* c00 = (const float4*)(g_aff2p + (size_t)(iy *W2+ix )*K);
        const float4* c01 = (const float4*)(g_aff2p + (size_t)(iy *W2+ix1)*K);
        const float4* c10 = (const float4*)(g_aff2p + (size_t)(iy1*W2+ix )*K);
        const float4* c11 = (const float4*)(g_aff2p + (size_t)(iy1*W2+ix1)*K);

        float mx = -1e30f;
        #pragma unroll
        for (int i = 0; i < 12; i++) {
            float4 q0 = c00[i], q1 = c01[i], q2 = c10[i], q3 = c11[i];
            mx = fmaxf(mx, q0.x*w00 + q1.x*w01 + q2.x*w10 + q3.x*w11);
            mx = fmaxf(mx, q0.y*w00 + q1.y*w01 + q2.y*w10 + q3.y*w11);
            mx = fmaxf(mx, q0.z*w00 + q1.z*w01 + q2.z*w10 + q3.z*w11);
            mx = fmaxf(mx, q0.w*w00 + q1.w*w01 + q2.w*w10 + q3.w*w11);
        }
        float es = 0.f;
        #pragma unroll
        for (int i = 0; i < 12; i++) {
            float4 q0 = c00[i], q1 = c01[i], q2 = c10[i], q3 = c11[i];
            es += __expf(q0.x*w00 + q1.x*w01 + q2.x*w10 + q3.x*w11 - mx);
            es += __expf(q0.y*w00 + q1.y*w01 + q2.y*w10 + q3.y*w11 - mx);
            es += __expf(q0.z*w00 + q1.z*w01 + q2.z*w10 + q3.z*w11 - mx);
            es += __expf(q0.w*w00 + q1.w*w01 + q2.w*w10 + q3.w*w11 - mx);
        }
        float inv = 1.f / es;
        #pragma unroll
        for (int i = 0; i < 12; i++) {
            float4 q0 = c00[i], q1 = c01[i], q2 = c10[i], q3 = c11[i];
            t[4*i+0] += __expf(q0.x*w00 + q1.x*w01 + q2.x*w10 + q3.x*w11 - mx) * inv + pos.v[4*i+0];
            t[4*i+1] += __expf(q0.y*w00 + q1.y*w01 + q2.y*w10 + q3.y*w11 - mx) * inv + pos.v[4*i+1];
            t[4*i+2] += __expf(q0.z*w00 + q1.z*w01 + q2.z*w10 + q3.z*w11 - mx) * inv + pos.v[4*i+2];
            t[4*i+3] += __expf(q0.w*w00 + q1.w*w01 + q2.w*w10 + q3.w*w11 - mx) * inv + pos.v[4*i+3];
        }
    }

    #pragma unroll
    for (int k = 0; k < K; k++) g_aff[(size_t)k*HW + p] = t[k];
}

// ---------------- propagation iteration: 2 px/thread, 3 channels, float2 ------
#define NCH 3

template<int D, bool WIN, bool HASC>
__device__ __forceinline__ void proc_row(const float* __restrict__ mbase, int dyoff,
                                         int k0, const float* __restrict__ affp,
                                         float acc[NCH][2]) {
    float2 aL = *(const float2*)(affp + (size_t)k0 * HW);
    float2 aR = *(const float2*)(affp + (size_t)(k0 + (HASC ? 2 : 1)) * HW);
    float2 aC = HASC ? *(const float2*)(affp + (size_t)(k0+1) * HW)
                     : make_float2(0.f, 0.f);
    #pragma unroll
    for (int c = 0; c < NCH; c++) {
        const float* r = mbase + c * PHW + dyoff;
        float2 vL, vC, vR;
        if (WIN) {
            float2 a = *(const float2*)(r - 2);
            float2 b = *(const float2*)(r);
            float2 e = *(const float2*)(r + 2);
            if (D == 1) {
                vL = make_float2(a.y, b.x);
                vR = make_float2(b.y, e.x);
            } else {
                vL = a;
                vR = e;
            }
            vC = b;
        } else {
            vL = *(const float2*)(r - D);
            vC = HASC ? *(const float2*)(r) : make_float2(0.f, 0.f);
            vR = *(const float2*)(r + D);
        }
        acc[c][0] = fmaf(aL.x, vL.x, acc[c][0]);
        acc[c][1] = fmaf(aL.y, vL.y, acc[c][1]);
        if (HASC) {
            acc[c][0] = fmaf(aC.x, vC.x, acc[c][0]);
            acc[c][1] = fmaf(aC.y, vC.y, acc[c][1]);
        }
        acc[c][0] = fmaf(aR.x, vR.x, acc[c][0]);
        acc[c][1] = fmaf(aR.y, vR.y, acc[c][1]);
    }
}

// block (112,4), grid (1, 56 or 58, 7): thread = 2 x-pixels, 3 channels.
// Blocks with blockIdx.y >= 56 are BORDER blocks: they recompute edge-pixel
// results directly from src (padded) and write the halo cells of dst.
// Interior blocks pay only one block-uniform branch.
__global__ __launch_bounds__(448) void iter_kernel(const float* __restrict__ src,
                                                   float* __restrict__ dst,
                                                   int pad_out) {
    const int tx = threadIdx.x, ty = threadIdx.y;
    const int c0 = blockIdx.z * NCH;

    if (blockIdx.y >= 56) {
        // ---- border block: 448 threads = 2 edges x 224 pixels ----
        const int tid  = ty * 112 + tx;
        const int half = tid / 224;       // 0: top/left, 1: bottom/right
        const int e    = tid - half * 224;
        int ex, ey;
        if (blockIdx.y == 56) { ex = e; ey = half ? (H-1) : 0; }   // top/bottom
        else                  { ey = e; ex = half ? (W-1) : 0; }   // left/right
        const int p  = ey * W + ex;
        const int pq = (ey + PAD) * PW + ex + PAD;

        const int DY[8] = {-1,-1,-1, 0, 0, 1, 1, 1};
        const int DX[8] = {-1, 0, 1,-1, 1,-1, 0, 1};
        const int DDc[6] = {1, 2, 4, 8, 12, 24};

        const float* __restrict__ m0 = src + (size_t)c0 * PHW + pq;
        float res[NCH] = {0.f, 0.f, 0.f};
        #pragma unroll
        for (int di = 0; di < 6; di++) {
            #pragma unroll
            for (int o = 0; o < 8; o++) {
                float a = g_aff[(size_t)(di*8+o) * HW + p];
                int off = DY[o]*DDc[di]*PW + DX[o]*DDc[di];
                res[0] = fmaf(a, m0[off], res[0]);
                res[1] = fmaf(a, m0[PHW + off], res[1]);
                res[2] = fmaf(a, m0[2*PHW + off], res[2]);
            }
        }

        const int wid = tid >> 5, lane = tid & 31;
        #pragma unroll
        for (int c = 0; c < NCH; c++) {
            float v = res[c];
            float* base = dst + (size_t)(c0+c) * PHW;
            if (blockIdx.y == 56) {
                // top/bottom halo strip: own column, 24 rows
                int rs = half ? (PAD + H) : 0;
                #pragma unroll 1
                for (int r = 0; r < PAD; r++)
                    base[(rs + r) * PW + ex + PAD] = v;
                // corners via warp-uniform shuffles
                if (wid == 0) {            // holds pixel (0,0) at lane 0
                    float cv = __shfl_sync(0xffffffffu, v, 0);
                    if (lane < PAD) {
                        #pragma unroll 1
                        for (int r = 0; r < PAD; r++)
                            base[r * PW + lane] = cv;
                    }
                }
                if (wid == 6) {            // holds pixel (0,223) at lane 31
                    float cv = __shfl_sync(0xffffffffu, v, 31);
                    if (lane >= 8) {
                        #pragma unroll 1
                        for (int r = 0; r < PAD; r++)
                            base[r * PW + (PAD + W) + (lane - 8)] = cv;
                    }
                }
                if (wid == 7) {            // holds pixel (223,0) at lane 0
                    float cv = __shfl_sync(0xffffffffu, v, 0);
                    if (lane < PAD) {
                        #pragma unroll 1
                        for (int r = 0; r < PAD; r++)
                            base[(PAD + H + r) * PW + lane] = cv;
                    }
                }
                if (wid == 13) {           // holds pixel (223,223) at lane 31
                    float cv = __shfl_sync(0xffffffffu, v, 31);
                    if (lane >= 8) {
                        #pragma unroll 1
                        for (int r = 0; r < PAD; r++)
                            base[(PAD + H + r) * PW + (PAD + W) + (lane - 8)] = cv;
                    }
                }
            } else {
                // left/right halo strip: own row, 24 cols (aligned float4)
                int js = half ? (PAD + W) : 0;
                float4 e4 = make_float4(v, v, v, v);
                #pragma unroll 1
                for (int j = 0; j < PAD; j += 4)
                    *(float4*)(base + (ey + PAD) * PW + js + j) = e4;
            }
        }
        return;
    }

    // ---- interior block (unchanged hot path) ----
    const int x2 = tx * 2;
    const int y  = blockIdx.y * 4 + ty;
    const int p  = y * W + x2;
    const int pp = (y + PAD) * PW + (x2 + PAD);

    const float* __restrict__ mbase = src + (size_t)c0 * PHW + pp;
    const float* __restrict__ affp  = g_aff + p;

    float acc[NCH][2];
    #pragma unroll
    for (int c = 0; c < NCH; c++) { acc[c][0] = 0.f; acc[c][1] = 0.f; }

    proc_row<1,  true,  true >(mbase, -1*PW,  0, affp, acc);
    proc_row<1,  true,  false>(mbase,  0,     3, affp, acc);
    proc_row<1,  true,  true >(mbase, +1*PW,  5, affp, acc);
    proc_row<2,  true,  true >(mbase, -2*PW,  8, affp, acc);
    proc_row<2,  true,  false>(mbase,  0,    11, affp, acc);
    proc_row<2,  true,  true >(mbase, +2*PW, 13, affp, acc);
    proc_row<4,  false, true >(mbase, -4*PW, 16, affp, acc);
    proc_row<4,  false, false>(mbase,  0,    19, affp, acc);
    proc_row<4,  false, true >(mbase, +4*PW, 21, affp, acc);
    proc_row<8,  false, true >(mbase, -8*PW, 24, affp, acc);
    proc_row<8,  false, false>(mbase,  0,    27, affp, acc);
    proc_row<8,  false, true >(mbase, +8*PW, 29, affp, acc);
    proc_row<12, false, true >(mbase, -12*PW, 32, affp, acc);
    proc_row<12, false, false>(mbase,  0,     35, affp, acc);
    proc_row<12, false, true >(mbase, +12*PW, 37, affp, acc);
    proc_row<24, false, true >(mbase, -24*PW, 40, affp, acc);
    proc_row<24, false, false>(mbase,  0,     43, affp, acc);
    proc_row<24, false, true >(mbase, +24*PW, 45, affp, acc);

    if (pad_out) {
        #pragma unroll
        for (int c = 0; c < NCH; c++)
            *(float2*)(dst + (size_t)(c0+c)*PHW + pp) = make_float2(acc[c][0], acc[c][1]);
    } else {
        #pragma unroll
        for (int c = 0; c < NCH; c++)
            *(float2*)(dst + (size_t)(c0+c)*HW + p) = make_float2(acc[c][0], acc[c][1]);
    }
}

// ---------------- host pos softmax --------------------------------------------
static PosArr make_pos_host() {
    const float s2 = sqrtf(2.0f);
    const float base[8] = {s2, 1.f, s2, 1.f, 1.f, s2, 1.f, s2};
    const int DD[6] = {1, 2, 4, 8, 12, 24};
    float pos[K];
    float sum = 0.f;
    for (int di = 0; di < 6; di++)
        for (int o = 0; o < 8; o++) {
            float v = base[o] * (float)DD[di];
            pos[di*8+o] = v; sum += v;
        }
    float mean = sum / 48.f, ss = 0.f;
    for (int k = 0; k < K; k++) { float d = pos[k] - mean; ss += d * d; }
    float sd = sqrtf(ss / 47.f);
    float mx = -1e30f;
    for (int k = 0; k < K; k++) {
        float t = pos[k] / ((sd + EPSF) * W1F);
        pos[k] = -t * t;
        if (pos[k] > mx) mx = pos[k];
    }
    float es = 0.f;
    for (int k = 0; k < K; k++) { pos[k] = expf(pos[k] - mx); es += pos[k]; }
    PosArr out;
    for (int k = 0; k < K; k++) out.v[k] = pos[k] / es;
    return out;
}

// ---------------- launch ------------------------------------------------------
extern "C" void kernel_launch(void* const* d_in, const int* in_sizes, int n_in,
                              void* d_out, int out_size) {
    const float* imgs  = (const float*)d_in[0];
    const float* masks = (const float*)d_in[1];
    if (n_in >= 2 && in_sizes[0] == C*MH*MW) {
        const float* t = imgs; imgs = masks; masks = t;
    }
    float *buf0, *buf1;
    cudaGetSymbolAddress((void**)&buf0, g_pad0);
    cudaGetSymbolAddress((void**)&buf1, g_pad1);

    PosArr pos = make_pos_host();

    const int PREP_N = C*PHW + 3*PHW + 3*HW2;
    prep_kernel<<<(PREP_N + 255)/256, 256>>>(imgs, masks);
    aff2_kernel<<<(HW2 + 31)/32, 32>>>();
    aff1up_kernel<<<dim3(7, 56), dim3(32, 4)>>>(pos);

    const float* src = buf0;
    for (int i = 0; i < 10; i++) {
        int last = (i == 9);
        float* dst = last ? (float*)d_out : ((i & 1) ? buf0 : buf1);
        iter_kernel<<<dim3(1, last ? 56 : 58, 7), dim3(112, 4)>>>(src, dst, !last);
        src = dst;
    }
}

// round 14
// speedup vs baseline: 1.4460x; 1.4460x over previous
#include <cuda_runtime.h>
#include <math.h>

#define H    224
#define W    224
#define HW   (224*224)
#define C    21
#define K    48
#define H2   67
#define W2   67
#define HW2  (67*67)
#define MH   56
#define MW   56
#define PAD  24
#define RW   272              // mask row width: 24 | 224 | 24 (horizontal halo only)
#define CHW  (224*272)        // per-channel mask buffer size
#define PW   272              // padded image (both axes) for aff1up precompute
#define PHW  (272*272)
#define EPSF 1e-8f
#define W1F  0.3f

// ---------------- device scratch ----------------
__device__ __align__(16) float g_m0[C*CHW];      // masks, horiz-padded rows
__device__ __align__(16) float g_m1[C*CHW];
__device__ __align__(16) float g_imgp[3*PHW];    // imgs padded both axes (precompute only)
__device__ __align__(16) float g_aff [K*HW];     // K-MAJOR: [k][p]
__device__ __align__(16) float g_imgs2[3*HW2];
__device__ __align__(16) float g_aff2p[HW2*K];   // pixel-major [p2][k]

struct PosArr { float v[K]; };

__device__ __forceinline__ int clampi(int v, int lo, int hi) {
    return v < lo ? lo : (v > hi ? hi : v);
}

// ---------------- fused prep: upmask->m0 (horiz pad), padimg, downimg ---------
__global__ void prep_kernel(const float* __restrict__ imgs,
                            const float* __restrict__ masks) {
    int idx = blockIdx.x * blockDim.x + threadIdx.x;
    if (idx < C*CHW) {
        int c = idx / CHW;
        int q = idx - c * CHW;
        int y  = q / RW;
        int px = q - y * RW;
        int x = clampi(px - PAD, 0, W-1);
        float fy = (float)y * (55.f / 223.f);
        int y0 = (int)fy; float wy = fy - (float)y0; int y1 = min(y0 + 1, 55);
        float fx = (float)x * (55.f / 223.f);
        int x0 = (int)fx; float wx = fx - (float)x0; int x1 = min(x0 + 1, 55);
        const float* mc = masks + c * MH * MW;
        float r0 = mc[y0*MW+x0] * (1.f - wy) + mc[y1*MW+x0] * wy;
        float r1 = mc[y0*MW+x1] * (1.f - wy) + mc[y1*MW+x1] * wy;
        g_m0[idx] = r0 * (1.f - wx) + r1 * wx;
        return;
    }
    idx -= C*CHW;
    if (idx < 3*PHW) {
        int c = idx / PHW;
        int q = idx - c * PHW;
        int py = q / PW, px = q - py * PW;
        int y = clampi(py - PAD, 0, H-1);
        int x = clampi(px - PAD, 0, W-1);
        g_imgp[idx] = imgs[c*HW + y*W + x];
        return;
    }
    idx -= 3*PHW;
    if (idx < 3*HW2) {
        int c = idx / HW2;
        int p = idx - c * HW2;
        int y = p / W2, x = p - y * W2;
        float fy = (float)y * (223.f / 66.f);
        int y0 = (int)fy; float wy = fy - (float)y0; int y1 = min(y0 + 1, 223);
        float fx = (float)x * (223.f / 66.f);
        int x0 = (int)fx; float wx = fx - (float)x0; int x1 = min(x0 + 1, 223);
        const float* ic = imgs + c * HW;
        float r0 = ic[y0*W+x0] * (1.f - wy) + ic[y1*W+x0] * wy;
        float r1 = ic[y0*W+x1] * (1.f - wy) + ic[y1*W+x1] * wy;
        g_imgs2[idx] = r0 * (1.f - wx) + r1 * wx;
    }
}

#define NB_ADDR(o, DI) \
    ((o)==0 ? rm[DI]+cm[DI] : (o)==1 ? rm[DI]+x   : (o)==2 ? rm[DI]+cp[DI] : \
     (o)==3 ? r0v  +cm[DI] : (o)==4 ? r0v  +cp[DI] : \
     (o)==5 ? rp[DI]+cm[DI] : (o)==6 ? rp[DI]+x   :            rp[DI]+cp[DI])

// ---------------- low-res affinity, pixel-major out ---------------------------
__global__ __launch_bounds__(32) void aff2_kernel() {
    int p = blockIdx.x * blockDim.x + threadIdx.x;
    if (p >= HW2) return;
    int y = p / W2, x = p - y * W2;
    const int DDc[6] = {1, 2, 4, 8, 12, 24};
    int rm[6], rp[6], cm[6], cp[6];
    #pragma unroll
    for (int di = 0; di < 6; di++) {
        int d = DDc[di];
        rm[di] = max(y - d, 0) * W2;
        rp[di] = min(y + d, H2-1) * W2;
        cm[di] = max(x - d, 0);
        cp[di] = min(x + d, W2-1);
    }
    int r0v = y * W2;

    float t[K];
    #pragma unroll
    for (int k = 0; k < K; k++) t[k] = 0.f;

    for (int c = 0; c < 3; c++) {
        const float* __restrict__ im = g_imgs2 + c * HW2;
        float ctr = im[p];
        float sum = 0.f, ss = 0.f;
        #pragma unroll
        for (int di = 0; di < 6; di++) {
            #pragma unroll
            for (int o = 0; o < 8; o++) {
                float v = im[NB_ADDR(o, di)];
                sum += v; ss = fmaf(v, v, ss);
            }
        }
        float mean = sum * (1.f/48.f);
        float var  = fmaxf((ss - sum * mean) * (1.f/47.f), 0.f);
        float inv  = 1.f / (sqrtf(var) + EPSF);
        float inv2 = inv * inv;
        #pragma unroll
        for (int di = 0; di < 6; di++) {
            #pragma unroll
            for (int o = 0; o < 8; o++) {
                float d = im[NB_ADDR(o, di)] - ctr;
                t[di*8+o] = fmaf(d * d, inv2, t[di*8+o]);
            }
        }
    }
    #pragma unroll
    for (int k = 0; k < K; k++) g_aff2p[p*K + k] = -t[k] * (1.f/3.f);
}

// ------- fused: fullres affinity softmax + upsampled aff2 softmax + pos -------
__global__ __launch_bounds__(128) void aff1up_kernel(PosArr pos) {
    const int x = blockIdx.x * 32 + threadIdx.x;
    const int y = blockIdx.y * 4  + threadIdx.y;
    const int p = y * W + x;
    const int pp = (y + PAD) * PW + (x + PAD);

    const int DY[8] = {-1,-1,-1, 0, 0, 1, 1, 1};
    const int DX[8] = {-1, 0, 1,-1, 1,-1, 0, 1};
    const int DDc[6] = {1, 2, 4, 8, 12, 24};

    float t[K];
    #pragma unroll
    for (int k = 0; k < K; k++) t[k] = 0.f;

    #pragma unroll 1
    for (int c = 0; c < 3; c++) {
        const float* __restrict__ im = g_imgp + c * PHW + pp;
        float ctr = im[0];
        float sum = 0.f, ss = 0.f;
        #pragma unroll
        for (int di = 0; di < 6; di++) {
            #pragma unroll
            for (int o = 0; o < 8; o++) {
                float v = im[DY[o]*DDc[di]*PW + DX[o]*DDc[di]];
                sum += v; ss = fmaf(v, v, ss);
            }
        }
        float mean = sum * (1.f/48.f);
        float var  = fmaxf((ss - sum * mean) * (1.f/47.f), 0.f);
        float inv  = 1.f / ((sqrtf(var) + EPSF) * W1F);
        float inv2 = inv * inv;
        #pragma unroll
        for (int di = 0; di < 6; di++) {
            #pragma unroll
            for (int o = 0; o < 8; o++) {
                float d = im[DY[o]*DDc[di]*PW + DX[o]*DDc[di]] - ctr;
                t[di*8+o] = fmaf(d * d, inv2, t[di*8+o]);
            }
        }
    }
    {
        float mx = -1e30f;
        #pragma unroll
        for (int k = 0; k < K; k++) { t[k] = -t[k] * (1.f/3.f); mx = fmaxf(mx, t[k]); }
        float es = 0.f;
        #pragma unroll
        for (int k = 0; k < K; k++) { t[k] = __expf(t[k] - mx); es += t[k]; }
        float inv = 1.f / es;
        #pragma unroll
        for (int k = 0; k < K; k++) t[k] *= inv;
    }

    {
        float fy = (float)y * (66.f / 223.f);
        int iy = (int)fy; float wy = fy - (float)iy; int iy1 = min(iy + 1, 66);
        float fx = (float)x * (66.f / 223.f);
        int ix = (int)fx; float wx = fx - (float)ix; int ix1 = min(ix + 1, 66);
        float w00 = (1.f-wy)*(1.f-wx), w01 = (1.f-wy)*wx;
        float w10 = wy*(1.f-wx),       w11 = wy*wx;

        const float4* c00 = (const float4*)(g_aff2p + (size_t)(iy *W2+ix )*K);
        const float4* c01 = (const float4*)(g_aff2p + (size_t)(iy *W2+ix1)*K);
        const float4* c10 = (const float4*)(g_aff2p + (size_t)(iy1*W2+ix )*K);
        const float4* c11 = (const float4*)(g_aff2p + (size_t)(iy1*W2+ix1)*K);

        float mx = -1e30f;
        #pragma unroll
        for (int i = 0; i < 12; i++) {
            float4 q0 = c00[i], q1 = c01[i], q2 = c10[i], q3 = c11[i];
            mx = fmaxf(mx, q0.x*w00 + q1.x*w01 + q2.x*w10 + q3.x*w11);
            mx = fmaxf(mx, q0.y*w00 + q1.y*w01 + q2.y*w10 + q3.y*w11);
            mx = fmaxf(mx, q0.z*w00 + q1.z*w01 + q2.z*w10 + q3.z*w11);
            mx = fmaxf(mx, q0.w*w00 + q1.w*w01 + q2.w*w10 + q3.w*w11);
        }
        float es = 0.f;
        #pragma unroll
        for (int i = 0; i < 12; i++) {
            float4 q0 = c00[i], q1 = c01[i], q2 = c10[i], q3 = c11[i];
            es += __expf(q0.x*w00 + q1.x*w01 + q2.x*w10 + q3.x*w11 - mx);
            es += __expf(q0.y*w00 + q1.y*w01 + q2.y*w10 + q3.y*w11 - mx);
            es += __expf(q0.z*w00 + q1.z*w01 + q2.z*w10 + q3.z*w11 - mx);
            es += __expf(q0.w*w00 + q1.w*w01 + q2.w*w10 + q3.w*w11 - mx);
        }
        float inv = 1.f / es;
        #pragma unroll
        for (int i = 0; i < 12; i++) {
            float4 q0 = c00[i], q1 = c01[i], q2 = c10[i], q3 = c11[i];
            t[4*i+0] += __expf(q0.x*w00 + q1.x*w01 + q2.x*w10 + q3.x*w11 - mx) * inv + pos.v[4*i+0];
            t[4*i+1] += __expf(q0.y*w00 + q1.y*w01 + q2.y*w10 + q3.y*w11 - mx) * inv + pos.v[4*i+1];
            t[4*i+2] += __expf(q0.z*w00 + q1.z*w01 + q2.z*w10 + q3.z*w11 - mx) * inv + pos.v[4*i+2];
            t[4*i+3] += __expf(q0.w*w00 + q1.w*w01 + q2.w*w10 + q3.w*w11 - mx) * inv + pos.v[4*i+3];
        }
    }

    #pragma unroll
    for (int k = 0; k < K; k++) g_aff[(size_t)k*HW + p] = t[k];
}

// ---------------- propagation iteration: 2 px/thread, 3 channels, float2 ------
// Mask layout: [C][224][272] — horizontal halo only; vertical handled by
// runtime-clamped row offsets (ru/rd) fed into proc_row's dyoff.
#define NCH 3

template<int D, bool WIN, bool HASC>
__device__ __forceinline__ void proc_row(const float* __restrict__ mbase, int dyoff,
                                         int k0, const float* __restrict__ affp,
                                         float acc[NCH][2]) {
    float2 aL = *(const float2*)(affp + (size_t)k0 * HW);
    float2 aR = *(const float2*)(affp + (size_t)(k0 + (HASC ? 2 : 1)) * HW);
    float2 aC = HASC ? *(const float2*)(affp + (size_t)(k0+1) * HW)
                     : make_float2(0.f, 0.f);
    #pragma unroll
    for (int c = 0; c < NCH; c++) {
        const float* r = mbase + c * CHW + dyoff;
        float2 vL, vC, vR;
        if (WIN) {
            float2 a = *(const float2*)(r - 2);
            float2 b = *(const float2*)(r);
            float2 e = *(const float2*)(r + 2);
            if (D == 1) {
                vL = make_float2(a.y, b.x);
                vR = make_float2(b.y, e.x);
            } else {
                vL = a;
                vR = e;
            }
            vC = b;
        } else {
            vL = *(const float2*)(r - D);
            vC = HASC ? *(const float2*)(r) : make_float2(0.f, 0.f);
            vR = *(const float2*)(r + D);
        }
        acc[c][0] = fmaf(aL.x, vL.x, acc[c][0]);
        acc[c][1] = fmaf(aL.y, vL.y, acc[c][1]);
        if (HASC) {
            acc[c][0] = fmaf(aC.x, vC.x, acc[c][0]);
            acc[c][1] = fmaf(aC.y, vC.y, acc[c][1]);
        }
        acc[c][0] = fmaf(aR.x, vR.x, acc[c][0]);
        acc[c][1] = fmaf(aR.y, vR.y, acc[c][1]);
    }
}

#define DIL_GROUP(D, WINF, K0) { \
    const int ru = -min(D, y) * RW; \
    const int rd =  min(D, H-1-y) * RW; \
    proc_row<D, WINF, true >(mbase, ru, K0,   affp, acc); \
    proc_row<D, WINF, false>(mbase, 0,  K0+3, affp, acc); \
    proc_row<D, WINF, true >(mbase, rd, K0+5, affp, acc); \
}

// block (112,2), grid (1,112,7): thread = 2 consecutive x-pixels, 3 channels.
__global__ __launch_bounds__(224) void iter_kernel(const float* __restrict__ src,
                                                   float* __restrict__ dst,
                                                   int pad_out) {
    const int tx = threadIdx.x;
    const int x2 = tx * 2;
    const int y  = blockIdx.y * 2 + threadIdx.y;
    const int p  = y * W + x2;
    const int c0 = blockIdx.z * NCH;

    const float* __restrict__ mbase = src + (size_t)c0 * CHW + y * RW + PAD + x2;
    const float* __restrict__ affp  = g_aff + p;

    float acc[NCH][2];
    #pragma unroll
    for (int c = 0; c < NCH; c++) { acc[c][0] = 0.f; acc[c][1] = 0.f; }

    DIL_GROUP(1,  true,  0)
    DIL_GROUP(2,  true,  8)
    DIL_GROUP(4,  false, 16)
    DIL_GROUP(8,  false, 24)
    DIL_GROUP(12, false, 32)
    DIL_GROUP(24, false, 40)

    if (pad_out) {
        #pragma unroll
        for (int c = 0; c < NCH; c++) {
            float2 v = make_float2(acc[c][0], acc[c][1]);
            float* row = dst + (size_t)(c0+c)*CHW + y * RW;
            *(float2*)(row + PAD + x2) = v;
            if (tx == 0) {                     // left halo cols 0..23
                float2 e = make_float2(v.x, v.x);
                #pragma unroll 1
                for (int j = 0; j < PAD; j += 2)
                    *(float2*)(row + j) = e;
            }
            if (tx == 111) {                   // right halo cols 248..271
                float2 e = make_float2(v.y, v.y);
                #pragma unroll 1
                for (int j = PAD + W; j < RW; j += 2)
                    *(float2*)(row + j) = e;
            }
        }
    } else {
        #pragma unroll
        for (int c = 0; c < NCH; c++)
            *(float2*)(dst + (size_t)(c0+c)*HW + p) = make_float2(acc[c][0], acc[c][1]);
    }
}

// ---------------- host pos softmax --------------------------------------------
static PosArr make_pos_host() {
    const float s2 = sqrtf(2.0f);
    const float base[8] = {s2, 1.f, s2, 1.f, 1.f, s2, 1.f, s2};
    const int DD[6] = {1, 2, 4, 8, 12, 24};
    float pos[K];
    float sum = 0.f;
    for (int di = 0; di < 6; di++)
        for (int o = 0; o < 8; o++) {
            float v = base[o] * (float)DD[di];
            pos[di*8+o] = v; sum += v;
        }
    float mean = sum / 48.f, ss = 0.f;
    for (int k = 0; k < K; k++) { float d = pos[k] - mean; ss += d * d; }
    float sd = sqrtf(ss / 47.f);
    float mx = -1e30f;
    for (int k = 0; k < K; k++) {
        float t = pos[k] / ((sd + EPSF) * W1F);
        pos[k] = -t * t;
        if (pos[k] > mx) mx = pos[k];
    }
    float es = 0.f;
    for (int k = 0; k < K; k++) { pos[k] = expf(pos[k] - mx); es += pos[k]; }
    PosArr out;
    for (int k = 0; k < K; k++) out.v[k] = pos[k] / es;
    return out;
}

// ---------------- launch ------------------------------------------------------
extern "C" void kernel_launch(void* const* d_in, const int* in_sizes, int n_in,
                              void* d_out, int out_size) {
    const float* imgs  = (const float*)d_in[0];
    const float* masks = (const float*)d_in[1];
    if (n_in >= 2 && in_sizes[0] == C*MH*MW) {
        const float* t = imgs; imgs = masks; masks = t;
    }
    float *buf0, *buf1;
    cudaGetSymbolAddress((void**)&buf0, g_m0);
    cudaGetSymbolAddress((void**)&buf1, g_m1);

    PosArr pos = make_pos_host();

    const int PREP_N = C*CHW + 3*PHW + 3*HW2;
    prep_kernel<<<(PREP_N + 255)/256, 256>>>(imgs, masks);
    aff2_kernel<<<(HW2 + 31)/32, 32>>>();
    aff1up_kernel<<<dim3(7, 56), dim3(32, 4)>>>(pos);

    const float* src = buf0;
    for (int i = 0; i < 10; i++) {
        int last = (i == 9);
        float* dst = last ? (float*)d_out : ((i & 1) ? buf0 : buf1);
        iter_kernel<<<dim3(1, 112, 7), dim3(112, 2)>>>(src, dst, !last);
        src = dst;
    }
}

// round 15
// speedup vs baseline: 2.9888x; 2.0668x over previous
#include <cuda_runtime.h>
#include <math.h>

#define H    224
#define W    224
#define HW   (224*224)
#define C    21
#define K    48
#define H2   67
#define W2   67
#define HW2  (67*67)
#define MH   56
#define MW   56
#define PAD  24
#define PW   272
#define PHW  (272*272)
#define EPSF 1e-8f
#define W1F  0.3f

// ---------------- device scratch ----------------
__device__ __align__(16) float g_pad0[C*PHW];
__device__ __align__(16) float g_pad1[C*PHW];
__device__ __align__(16) float g_imgp[3*PHW];
__device__ __align__(16) float g_aff [K*HW];     // K-MAJOR: [k][p]
__device__ __align__(16) float g_imgs2[3*HW2];
__device__ __align__(16) float g_aff2p[HW2*K];   // pixel-major [p2][k]

struct PosArr { float v[K]; };

__device__ __forceinline__ int clampi(int v, int lo, int hi) {
    return v < lo ? lo : (v > hi ? hi : v);
}

// ---------------- fused prep: upmask->pad0, padimg, downimg -------------------
__global__ void prep_kernel(const float* __restrict__ imgs,
                            const float* __restrict__ masks) {
    int idx = blockIdx.x * blockDim.x + threadIdx.x;
    if (idx < C*PHW) {
        int c = idx / PHW;
        int q = idx - c * PHW;
        int py = q / PW, px = q - py * PW;
        int y = clampi(py - PAD, 0, H-1);
        int x = clampi(px - PAD, 0, W-1);
        float fy = (float)y * (55.f / 223.f);
        int y0 = (int)fy; float wy = fy - (float)y0; int y1 = min(y0 + 1, 55);
        float fx = (float)x * (55.f / 223.f);
        int x0 = (int)fx; float wx = fx - (float)x0; int x1 = min(x0 + 1, 55);
        const float* mc = masks + c * MH * MW;
        float r0 = mc[y0*MW+x0] * (1.f - wy) + mc[y1*MW+x0] * wy;
        float r1 = mc[y0*MW+x1] * (1.f - wy) + mc[y1*MW+x1] * wy;
        g_pad0[idx] = r0 * (1.f - wx) + r1 * wx;
        return;
    }
    idx -= C*PHW;
    if (idx < 3*PHW) {
        int c = idx / PHW;
        int q = idx - c * PHW;
        int py = q / PW, px = q - py * PW;
        int y = clampi(py - PAD, 0, H-1);
        int x = clampi(px - PAD, 0, W-1);
        g_imgp[idx] = imgs[c*HW + y*W + x];
        return;
    }
    idx -= 3*PHW;
    if (idx < 3*HW2) {
        int c = idx / HW2;
        int p = idx - c * HW2;
        int y = p / W2, x = p - y * W2;
        float fy = (float)y * (223.f / 66.f);
        int y0 = (int)fy; float wy = fy - (float)y0; int y1 = min(y0 + 1, 223);
        float fx = (float)x * (223.f / 66.f);
        int x0 = (int)fx; float wx = fx - (float)x0; int x1 = min(x0 + 1, 223);
        const float* ic = imgs + c * HW;
        float r0 = ic[y0*W+x0] * (1.f - wy) + ic[y1*W+x0] * wy;
        float r1 = ic[y0*W+x1] * (1.f - wy) + ic[y1*W+x1] * wy;
        g_imgs2[idx] = r0 * (1.f - wx) + r1 * wx;
    }
}

#define NB_ADDR(o, DI) \
    ((o)==0 ? rm[DI]+cm[DI] : (o)==1 ? rm[DI]+x   : (o)==2 ? rm[DI]+cp[DI] : \
     (o)==3 ? r0v  +cm[DI] : (o)==4 ? r0v  +cp[DI] : \
     (o)==5 ? rp[DI]+cm[DI] : (o)==6 ? rp[DI]+x   :            rp[DI]+cp[DI])

// ---------------- low-res affinity, pixel-major out ---------------------------
// 32-thread blocks -> 141 blocks, spreads across all SMs.
__global__ __launch_bounds__(32) void aff2_kernel() {
    int p = blockIdx.x * blockDim.x + threadIdx.x;
    if (p >= HW2) return;
    int y = p / W2, x = p - y * W2;
    const int DDc[6] = {1, 2, 4, 8, 12, 24};
    int rm[6], rp[6], cm[6], cp[6];
    #pragma unroll
    for (int di = 0; di < 6; di++) {
        int d = DDc[di];
        rm[di] = max(y - d, 0) * W2;
        rp[di] = min(y + d, H2-1) * W2;
        cm[di] = max(x - d, 0);
        cp[di] = min(x + d, W2-1);
    }
    int r0v = y * W2;

    float t[K];
    #pragma unroll
    for (int k = 0; k < K; k++) t[k] = 0.f;

    for (int c = 0; c < 3; c++) {
        const float* __restrict__ im = g_imgs2 + c * HW2;
        float ctr = im[p];
        float sum = 0.f, ss = 0.f;
        #pragma unroll
        for (int di = 0; di < 6; di++) {
            #pragma unroll
            for (int o = 0; o < 8; o++) {
                float v = im[NB_ADDR(o, di)];
                sum += v; ss = fmaf(v, v, ss);
            }
        }
        float mean = sum * (1.f/48.f);
        float var  = fmaxf((ss - sum * mean) * (1.f/47.f), 0.f);
        float inv  = 1.f / (sqrtf(var) + EPSF);
        float inv2 = inv * inv;
        #pragma unroll
        for (int di = 0; di < 6; di++) {
            #pragma unroll
            for (int o = 0; o < 8; o++) {
                float d = im[NB_ADDR(o, di)] - ctr;
                t[di*8+o] = fmaf(d * d, inv2, t[di*8+o]);
            }
        }
    }
    #pragma unroll
    for (int k = 0; k < K; k++) g_aff2p[p*K + k] = -t[k] * (1.f/3.f);
}

// ------- fused: fullres affinity softmax + upsampled aff2 softmax + pos -------
__global__ __launch_bounds__(128) void aff1up_kernel(PosArr pos) {
    const int x = blockIdx.x * 32 + threadIdx.x;
    const int y = blockIdx.y * 4  + threadIdx.y;
    const int p = y * W + x;
    const int pp = (y + PAD) * PW + (x + PAD);

    const int DY[8] = {-1,-1,-1, 0, 0, 1, 1, 1};
    const int DX[8] = {-1, 0, 1,-1, 1,-1, 0, 1};
    const int DDc[6] = {1, 2, 4, 8, 12, 24};

    float t[K];
    #pragma unroll
    for (int k = 0; k < K; k++) t[k] = 0.f;

    #pragma unroll 1
    for (int c = 0; c < 3; c++) {
        const float* __restrict__ im = g_imgp + c * PHW + pp;
        float ctr = im[0];
        float sum = 0.f, ss = 0.f;
        #pragma unroll
        for (int di = 0; di < 6; di++) {
            #pragma unroll
            for (int o = 0; o < 8; o++) {
                float v = im[DY[o]*DDc[di]*PW + DX[o]*DDc[di]];
                sum += v; ss = fmaf(v, v, ss);
            }
        }
        float mean = sum * (1.f/48.f);
        float var  = fmaxf((ss - sum * mean) * (1.f/47.f), 0.f);
        float inv  = 1.f / ((sqrtf(var) + EPSF) * W1F);
        float inv2 = inv * inv;
        #pragma unroll
        for (int di = 0; di < 6; di++) {
            #pragma unroll
            for (int o = 0; o < 8; o++) {
                float d = im[DY[o]*DDc[di]*PW + DX[o]*DDc[di]] - ctr;
                t[di*8+o] = fmaf(d * d, inv2, t[di*8+o]);
            }
        }
    }
    {
        float mx = -1e30f;
        #pragma unroll
        for (int k = 0; k < K; k++) { t[k] = -t[k] * (1.f/3.f); mx = fmaxf(mx, t[k]); }
        float es = 0.f;
        #pragma unroll
        for (int k = 0; k < K; k++) { t[k] = __expf(t[k] - mx); es += t[k]; }
        float inv = 1.f / es;
        #pragma unroll
        for (int k = 0; k < K; k++) t[k] *= inv;
    }

    {
        float fy = (float)y * (66.f / 223.f);
        int iy = (int)fy; float wy = fy - (float)iy; int iy1 = min(iy + 1, 66);
        float fx = (float)x * (66.f / 223.f);
        int ix = (int)fx; float wx = fx - (float)ix; int ix1 = min(ix + 1, 66);
        float w00 = (1.f-wy)*(1.f-wx), w01 = (1.f-wy)*wx;
        float w10 = wy*(1.f-wx),       w11 = wy*wx;

        const float4* c00 = (const float4*)(g_aff2p + (size_t)(iy *W2+ix )*K);
        const float4* c01 = (const float4*)(g_aff2p + (size_t)(iy *W2+ix1)*K);
        const float4* c10 = (const float4*)(g_aff2p + (size_t)(iy1*W2+ix )*K);
        const float4* c11 = (const float4*)(g_aff2p + (size_t)(iy1*W2+ix1)*K);

        float mx = -1e30f;
        #pragma unroll
        for (int i = 0; i < 12; i++) {
            float4 q0 = c00[i], q1 = c01[i], q2 = c10[i], q3 = c11[i];
            mx = fmaxf(mx, q0.x*w00 + q1.x*w01 + q2.x*w10 + q3.x*w11);
            mx = fmaxf(mx, q0.y*w00 + q1.y*w01 + q2.y*w10 + q3.y*w11);
            mx = fmaxf(mx, q0.z*w00 + q1.z*w01 + q2.z*w10 + q3.z*w11);
            mx = fmaxf(mx, q0.w*w00 + q1.w*w01 + q2.w*w10 + q3.w*w11);
        }
        float es = 0.f;
        #pragma unroll
        for (int i = 0; i < 12; i++) {
            float4 q0 = c00[i], q1 = c01[i], q2 = c10[i], q3 = c11[i];
            es += __expf(q0.x*w00 + q1.x*w01 + q2.x*w10 + q3.x*w11 - mx);
            es += __expf(q0.y*w00 + q1.y*w01 + q2.y*w10 + q3.y*w11 - mx);
            es += __expf(q0.z*w00 + q1.z*w01 + q2.z*w10 + q3.z*w11 - mx);
            es += __expf(q0.w*w00 + q1.w*w01 + q2.w*w10 + q3.w*w11 - mx);
        }
        float inv = 1.f / es;
        #pragma unroll
        for (int i = 0; i < 12; i++) {
            float4 q0 = c00[i], q1 = c01[i], q2 = c10[i], q3 = c11[i];
            t[4*i+0] += __expf(q0.x*w00 + q1.x*w01 + q2.x*w10 + q3.x*w11 - mx) * inv + pos.v[4*i+0];
            t[4*i+1] += __expf(q0.y*w00 + q1.y*w01 + q2.y*w10 + q3.y*w11 - mx) * inv + pos.v[4*i+1];
            t[4*i+2] += __expf(q0.z*w00 + q1.z*w01 + q2.z*w10 + q3.z*w11 - mx) * inv + pos.v[4*i+2];
            t[4*i+3] += __expf(q0.w*w00 + q1.w*w01 + q2.w*w10 + q3.w*w11 - mx) * inv + pos.v[4*i+3];
        }
    }

    #pragma unroll
    for (int k = 0; k < K; k++) g_aff[(size_t)k*HW + p] = t[k];
}

// ---------------- propagation iteration: 2 px/thread, 3 channels, float2 ------
#define NCH 3

template<int D, bool WIN, bool HASC>
__device__ __forceinline__ void proc_row(const float* __restrict__ mbase, int dyoff,
                                         int k0, const float* __restrict__ affp,
                                         float acc[NCH][2]) {
    float2 aL = *(const float2*)(affp + (size_t)k0 * HW);
    float2 aR = *(const float2*)(affp + (size_t)(k0 + (HASC ? 2 : 1)) * HW);
    float2 aC = HASC ? *(const float2*)(affp + (size_t)(k0+1) * HW)
                     : make_float2(0.f, 0.f);
    #pragma unroll
    for (int c = 0; c < NCH; c++) {
        const float* r = mbase + c * PHW + dyoff;
        float2 vL, vC, vR;
        if (WIN) {
            float2 a = *(const float2*)(r - 2);
            float2 b = *(const float2*)(r);
            float2 e = *(const float2*)(r + 2);
            if (D == 1) {
                vL = make_float2(a.y, b.x);
                vR = make_float2(b.y, e.x);
            } else {
                vL = a;
                vR = e;
            }
            vC = b;
        } else {
            vL = *(const float2*)(r - D);
            vC = HASC ? *(const float2*)(r) : make_float2(0.f, 0.f);
            vR = *(const float2*)(r + D);
        }
        acc[c][0] = fmaf(aL.x, vL.x, acc[c][0]);
        acc[c][1] = fmaf(aL.y, vL.y, acc[c][1]);
        if (HASC) {
            acc[c][0] = fmaf(aC.x, vC.x, acc[c][0]);
            acc[c][1] = fmaf(aC.y, vC.y, acc[c][1]);
        }
        acc[c][0] = fmaf(aR.x, vR.x, acc[c][0]);
        acc[c][1] = fmaf(aR.y, vR.y, acc[c][1]);
    }
}

// block (112,2), grid (1,112,7): thread = 2 consecutive x-pixels, 3 channels.
__global__ __launch_bounds__(224) void iter_kernel(const float* __restrict__ src,
                                                   float* __restrict__ dst,
                                                   int pad_out) {
    const int x2 = threadIdx.x * 2;
    const int y  = blockIdx.y * 2 + threadIdx.y;
    const int p  = y * W + x2;
    const int pp = (y + PAD) * PW + (x2 + PAD);
    const int c0 = blockIdx.z * NCH;

    const float* __restrict__ mbase = src + (size_t)c0 * PHW + pp;
    const float* __restrict__ affp  = g_aff + p;

    float acc[NCH][2];
    #pragma unroll
    for (int c = 0; c < NCH; c++) { acc[c][0] = 0.f; acc[c][1] = 0.f; }

    proc_row<1,  true,  true >(mbase, -1*PW,  0, affp, acc);
    proc_row<1,  true,  false>(mbase,  0,     3, affp, acc);
    proc_row<1,  true,  true >(mbase, +1*PW,  5, affp, acc);
    proc_row<2,  true,  true >(mbase, -2*PW,  8, affp, acc);
    proc_row<2,  true,  false>(mbase,  0,    11, affp, acc);
    proc_row<2,  true,  true >(mbase, +2*PW, 13, affp, acc);
    proc_row<4,  false, true >(mbase, -4*PW, 16, affp, acc);
    proc_row<4,  false, false>(mbase,  0,    19, affp, acc);
    proc_row<4,  false, true >(mbase, +4*PW, 21, affp, acc);
    proc_row<8,  false, true >(mbase, -8*PW, 24, affp, acc);
    proc_row<8,  false, false>(mbase,  0,    27, affp, acc);
    proc_row<8,  false, true >(mbase, +8*PW, 29, affp, acc);
    proc_row<12, false, true >(mbase, -12*PW, 32, affp, acc);
    proc_row<12, false, false>(mbase,  0,     35, affp, acc);
    proc_row<12, false, true >(mbase, +12*PW, 37, affp, acc);
    proc_row<24, false, true >(mbase, -24*PW, 40, affp, acc);
    proc_row<24, false, false>(mbase,  0,     43, affp, acc);
    proc_row<24, false, true >(mbase, +24*PW, 45, affp, acc);

    if (pad_out) {
        #pragma unroll
        for (int c = 0; c < NCH; c++)
            *(float2*)(dst + (size_t)(c0+c)*PHW + pp) = make_float2(acc[c][0], acc[c][1]);
    } else {
        #pragma unroll
        for (int c = 0; c < NCH; c++)
            *(float2*)(dst + (size_t)(c0+c)*HW + p) = make_float2(acc[c][0], acc[c][1]);
    }
}

// ---------------- border-only replicate-pad refresh (float4 stripes) ----------
#define TB_N  (C*48*68)
#define SD_N  (C*224*12)
__global__ void padb_kernel(float* __restrict__ buf) {
    int idx = blockIdx.x * blockDim.x + threadIdx.x;
    if (idx < TB_N) {
        int c = idx / (48*68);
        int i = idx - c * (48*68);
        int r = i / 68, q4 = (i - r*68) * 4;
        int py = (r < 24) ? r : (r + 224);
        int y = clampi(py - PAD, 0, H-1);
        float4 v;
        v.x = buf[c*PHW + (y+PAD)*PW + clampi(q4+0-PAD, 0, W-1) + PAD];
        v.y = buf[c*PHW + (y+PAD)*PW + clampi(q4+1-PAD, 0, W-1) + PAD];
        v.z = buf[c*PHW + (y+PAD)*PW + clampi(q4+2-PAD, 0, W-1) + PAD];
        v.w = buf[c*PHW + (y+PAD)*PW + clampi(q4+3-PAD, 0, W-1) + PAD];
        *(float4*)(buf + c*PHW + py*PW + q4) = v;
        return;
    }
    idx -= TB_N;
    if (idx < SD_N) {
        int c = idx / (224*12);
        int i = idx - c * (224*12);
        int row = i / 12, s = i - row*12;
        int py = PAD + row;
        int q4 = (s < 6) ? s*4 : (PAD + W + (s-6)*4);
        float edge = (s < 6) ? buf[c*PHW + py*PW + PAD]
                             : buf[c*PHW + py*PW + PAD + W - 1];
        *(float4*)(buf + c*PHW + py*PW + q4) = make_float4(edge, edge, edge, edge);
    }
}

// ---------------- host pos softmax --------------------------------------------
static PosArr make_pos_host() {
    const float s2 = sqrtf(2.0f);
    const float base[8] = {s2, 1.f, s2, 1.f, 1.f, s2, 1.f, s2};
    const int DD[6] = {1, 2, 4, 8, 12, 24};
    float pos[K];
    float sum = 0.f;
    for (int di = 0; di < 6; di++)
        for (int o = 0; o < 8; o++) {
            float v = base[o] * (float)DD[di];
            pos[di*8+o] = v; sum += v;
        }
    float mean = sum / 48.f, ss = 0.f;
    for (int k = 0; k < K; k++) { float d = pos[k] - mean; ss += d * d; }
    float sd = sqrtf(ss / 47.f);
    float mx = -1e30f;
    for (int k = 0; k < K; k++) {
        float t = pos[k] / ((sd + EPSF) * W1F);
        pos[k] = -t * t;
        if (pos[k] > mx) mx = pos[k];
    }
    float es = 0.f;
    for (int k = 0; k < K; k++) { pos[k] = expf(pos[k] - mx); es += pos[k]; }
    PosArr out;
    for (int k = 0; k < K; k++) out.v[k] = pos[k] / es;
    return out;
}

// ---------------- launch ------------------------------------------------------
extern "C" void kernel_launch(void* const* d_in, const int* in_sizes, int n_in,
                              void* d_out, int out_size) {
    const float* imgs  = (const float*)d_in[0];
    const float* masks = (const float*)d_in[1];
    if (n_in >= 2 && in_sizes[0] == C*MH*MW) {
        const float* t = imgs; imgs = masks; masks = t;
    }
    float *buf0, *buf1;
    cudaGetSymbolAddress((void**)&buf0, g_pad0);
    cudaGetSymbolAddress((void**)&buf1, g_pad1);

    PosArr pos = make_pos_host();

    const int PREP_N = C*PHW + 3*PHW + 3*HW2;
    prep_kernel<<<(PREP_N + 255)/256, 256>>>(imgs, masks);
    aff2_kernel<<<(HW2 + 31)/32, 32>>>();
    aff1up_kernel<<<dim3(7, 56), dim3(32, 4)>>>(pos);

    const float* src = buf0;
    for (int i = 0; i < 10; i++) {
        int last = (i == 9);
        float* dst = last ? (float*)d_out : ((i & 1) ? buf0 : buf1);
        iter_kernel<<<dim3(1, 112, 7), dim3(112, 2)>>>(src, dst, !last);
        if (!last) padb_kernel<<<(TB_N + SD_N + 255)/256, 256>>>(dst);
        src = dst;
    }
}

// round 16
// speedup vs baseline: 3.1591x; 1.0570x over previous
#include <cuda_runtime.h>
#include <cuda_fp16.h>
#include <math.h>

#define H    224
#define W    224
#define HW   (224*224)
#define C    21
#define K    48
#define H2   67
#define W2   67
#define HW2  (67*67)
#define MH   56
#define MW   56
#define PAD  24
#define PW   272
#define PHW  (272*272)
#define EPSF 1e-8f
#define W1F  0.3f

// ---------------- device scratch ----------------
__device__ __align__(16) float  g_pad0[C*PHW];
__device__ __align__(16) float  g_pad1[C*PHW];
__device__ __align__(16) float  g_imgp[3*PHW];
__device__ __align__(16) __half g_aff [K*HW];    // K-MAJOR fp16: [k][p]
__device__ __align__(16) float  g_imgs2[3*HW2];
__device__ __align__(16) float  g_aff2p[HW2*K];  // pixel-major [p2][k]

struct PosArr { float v[K]; };

__device__ __forceinline__ int clampi(int v, int lo, int hi) {
    return v < lo ? lo : (v > hi ? hi : v);
}

// ---------------- fused prep: upmask->pad0, padimg, downimg -------------------
__global__ void prep_kernel(const float* __restrict__ imgs,
                            const float* __restrict__ masks) {
    int idx = blockIdx.x * blockDim.x + threadIdx.x;
    if (idx < C*PHW) {
        int c = idx / PHW;
        int q = idx - c * PHW;
        int py = q / PW, px = q - py * PW;
        int y = clampi(py - PAD, 0, H-1);
        int x = clampi(px - PAD, 0, W-1);
        float fy = (float)y * (55.f / 223.f);
        int y0 = (int)fy; float wy = fy - (float)y0; int y1 = min(y0 + 1, 55);
        float fx = (float)x * (55.f / 223.f);
        int x0 = (int)fx; float wx = fx - (float)x0; int x1 = min(x0 + 1, 55);
        const float* mc = masks + c * MH * MW;
        float r0 = mc[y0*MW+x0] * (1.f - wy) + mc[y1*MW+x0] * wy;
        float r1 = mc[y0*MW+x1] * (1.f - wy) + mc[y1*MW+x1] * wy;
        g_pad0[idx] = r0 * (1.f - wx) + r1 * wx;
        return;
    }
    idx -= C*PHW;
    if (idx < 3*PHW) {
        int c = idx / PHW;
        int q = idx - c * PHW;
        int py = q / PW, px = q - py * PW;
        int y = clampi(py - PAD, 0, H-1);
        int x = clampi(px - PAD, 0, W-1);
        g_imgp[idx] = imgs[c*HW + y*W + x];
        return;
    }
    idx -= 3*PHW;
    if (idx < 3*HW2) {
        int c = idx / HW2;
        int p = idx - c * HW2;
        int y = p / W2, x = p - y * W2;
        float fy = (float)y * (223.f / 66.f);
        int y0 = (int)fy; float wy = fy - (float)y0; int y1 = min(y0 + 1, 223);
        float fx = (float)x * (223.f / 66.f);
        int x0 = (int)fx; float wx = fx - (float)x0; int x1 = min(x0 + 1, 223);
        const float* ic = imgs + c * HW;
        float r0 = ic[y0*W+x0] * (1.f - wy) + ic[y1*W+x0] * wy;
        float r1 = ic[y0*W+x1] * (1.f - wy) + ic[y1*W+x1] * wy;
        g_imgs2[idx] = r0 * (1.f - wx) + r1 * wx;
    }
}

#define NB_ADDR(o, DI) \
    ((o)==0 ? rm[DI]+cm[DI] : (o)==1 ? rm[DI]+x   : (o)==2 ? rm[DI]+cp[DI] : \
     (o)==3 ? r0v  +cm[DI] : (o)==4 ? r0v  +cp[DI] : \
     (o)==5 ? rp[DI]+cm[DI] : (o)==6 ? rp[DI]+x   :            rp[DI]+cp[DI])

// ---------------- low-res affinity, pixel-major out ---------------------------
__global__ __launch_bounds__(32) void aff2_kernel() {
    int p = blockIdx.x * blockDim.x + threadIdx.x;
    if (p >= HW2) return;
    int y = p / W2, x = p - y * W2;
    const int DDc[6] = {1, 2, 4, 8, 12, 24};
    int rm[6], rp[6], cm[6], cp[6];
    #pragma unroll
    for (int di = 0; di < 6; di++) {
        int d = DDc[di];
        rm[di] = max(y - d, 0) * W2;
        rp[di] = min(y + d, H2-1) * W2;
        cm[di] = max(x - d, 0);
        cp[di] = min(x + d, W2-1);
    }
    int r0v = y * W2;

    float t[K];
    #pragma unroll
    for (int k = 0; k < K; k++) t[k] = 0.f;

    for (int c = 0; c < 3; c++) {
        const float* __restrict__ im = g_imgs2 + c * HW2;
        float ctr = im[p];
        float sum = 0.f, ss = 0.f;
        #pragma unroll
        for (int di = 0; di < 6; di++) {
            #pragma unroll
            for (int o = 0; o < 8; o++) {
                float v = im[NB_ADDR(o, di)];
                sum += v; ss = fmaf(v, v, ss);
            }
        }
        float mean = sum * (1.f/48.f);
        float var  = fmaxf((ss - sum * mean) * (1.f/47.f), 0.f);
        float inv  = 1.f / (sqrtf(var) + EPSF);
        float inv2 = inv * inv;
        #pragma unroll
        for (int di = 0; di < 6; di++) {
            #pragma unroll
            for (int o = 0; o < 8; o++) {
                float d = im[NB_ADDR(o, di)] - ctr;
                t[di*8+o] = fmaf(d * d, inv2, t[di*8+o]);
            }
        }
    }
    #pragma unroll
    for (int k = 0; k < K; k++) g_aff2p[p*K + k] = -t[k] * (1.f/3.f);
}

// ------- fused: fullres affinity softmax + upsampled aff2 softmax + pos -------
// Writes K-MAJOR fp16 g_aff.
__global__ __launch_bounds__(128) void aff1up_kernel(PosArr pos) {
    const int x = blockIdx.x * 32 + threadIdx.x;
    const int y = blockIdx.y * 4  + threadIdx.y;
    const int p = y * W + x;
    const int pp = (y + PAD) * PW + (x + PAD);

    const int DY[8] = {-1,-1,-1, 0, 0, 1, 1, 1};
    const int DX[8] = {-1, 0, 1,-1, 1,-1, 0, 1};
    const int DDc[6] = {1, 2, 4, 8, 12, 24};

    float t[K];
    #pragma unroll
    for (int k = 0; k < K; k++) t[k] = 0.f;

    #pragma unroll 1
    for (int c = 0; c < 3; c++) {
        const float* __restrict__ im = g_imgp + c * PHW + pp;
        float ctr = im[0];
        float sum = 0.f, ss = 0.f;
        #pragma unroll
        for (int di = 0; di < 6; di++) {
            #pragma unroll
            for (int o = 0; o < 8; o++) {
                float v = im[DY[o]*DDc[di]*PW + DX[o]*DDc[di]];
                sum += v; ss = fmaf(v, v, ss);
            }
        }
        float mean = sum * (1.f/48.f);
        float var  = fmaxf((ss - sum * mean) * (1.f/47.f), 0.f);
        float inv  = 1.f / ((sqrtf(var) + EPSF) * W1F);
        float inv2 = inv * inv;
        #pragma unroll
        for (int di = 0; di < 6; di++) {
            #pragma unroll
            for (int o = 0; o < 8; o++) {
                float d = im[DY[o]*DDc[di]*PW + DX[o]*DDc[di]] - ctr;
                t[di*8+o] = fmaf(d * d, inv2, t[di*8+o]);
            }
        }
    }
    {
        float mx = -1e30f;
        #pragma unroll
        for (int k = 0; k < K; k++) { t[k] = -t[k] * (1.f/3.f); mx = fmaxf(mx, t[k]); }
        float es = 0.f;
        #pragma unroll
        for (int k = 0; k < K; k++) { t[k] = __expf(t[k] - mx); es += t[k]; }
        float inv = 1.f / es;
        #pragma unroll
        for (int k = 0; k < K; k++) t[k] *= inv;
    }

    {
        float fy = (float)y * (66.f / 223.f);
        int iy = (int)fy; float wy = fy - (float)iy; int iy1 = min(iy + 1, 66);
        float fx = (float)x * (66.f / 223.f);
        int ix = (int)fx; float wx = fx - (float)ix; int ix1 = min(ix + 1, 66);
        float w00 = (1.f-wy)*(1.f-wx), w01 = (1.f-wy)*wx;
        float w10 = wy*(1.f-wx),       w11 = wy*wx;

        const float4* c00 = (const float4*)(g_aff2p + (size_t)(iy *W2+ix )*K);
        const float4* c01 = (const float4*)(g_aff2p + (size_t)(iy *W2+ix1)*K);
        const float4* c10 = (const float4*)(g_aff2p + (size_t)(iy1*W2+ix )*K);
        const float4* c11 = (const float4*)(g_aff2p + (size_t)(iy1*W2+ix1)*K);

        float mx = -1e30f;
        #pragma unroll
        for (int i = 0; i < 12; i++) {
            float4 q0 = c00[i], q1 = c01[i], q2 = c10[i], q3 = c11[i];
            mx = fmaxf(mx, q0.x*w00 + q1.x*w01 + q2.x*w10 + q3.x*w11);
            mx = fmaxf(mx, q0.y*w00 + q1.y*w01 + q2.y*w10 + q3.y*w11);
            mx = fmaxf(mx, q0.z*w00 + q1.z*w01 + q2.z*w10 + q3.z*w11);
            mx = fmaxf(mx, q0.w*w00 + q1.w*w01 + q2.w*w10 + q3.w*w11);
        }
        float es = 0.f;
        #pragma unroll
        for (int i = 0; i < 12; i++) {
            float4 q0 = c00[i], q1 = c01[i], q2 = c10[i], q3 = c11[i];
            es += __expf(q0.x*w00 + q1.x*w01 + q2.x*w10 + q3.x*w11 - mx);
            es += __expf(q0.y*w00 + q1.y*w01 + q2.y*w10 + q3.y*w11 - mx);
            es += __expf(q0.z*w00 + q1.z*w01 + q2.z*w10 + q3.z*w11 - mx);
            es += __expf(q0.w*w00 + q1.w*w01 + q2.w*w10 + q3.w*w11 - mx);
        }
        float inv = 1.f / es;
        #pragma unroll
        for (int i = 0; i < 12; i++) {
            float4 q0 = c00[i], q1 = c01[i], q2 = c10[i], q3 = c11[i];
            t[4*i+0] += __expf(q0.x*w00 + q1.x*w01 + q2.x*w10 + q3.x*w11 - mx) * inv + pos.v[4*i+0];
            t[4*i+1] += __expf(q0.y*w00 + q1.y*w01 + q2.y*w10 + q3.y*w11 - mx) * inv + pos.v[4*i+1];
            t[4*i+2] += __expf(q0.z*w00 + q1.z*w01 + q2.z*w10 + q3.z*w11 - mx) * inv + pos.v[4*i+2];
            t[4*i+3] += __expf(q0.w*w00 + q1.w*w01 + q2.w*w10 + q3.w*w11 - mx) * inv + pos.v[4*i+3];
        }
    }

    #pragma unroll
    for (int k = 0; k < K; k++) g_aff[(size_t)k*HW + p] = __float2half_rn(t[k]);
}

// ---------------- propagation iteration: 2 px/thread, 3 channels, float2 ------
// aff in fp16 (half2 per 2 pixels). d1/d2 center rows fused (shared window).
#define NCH 3

__device__ __forceinline__ float2 affld(const __half* __restrict__ affp, int k) {
    return __half22float2(*(const __half2*)(affp + (size_t)k * HW));
}

template<int D, bool WIN, bool HASC>
__device__ __forceinline__ void proc_row(const float* __restrict__ mbase, int dyoff,
                                         int k0, const __half* __restrict__ affp,
                                         float acc[NCH][2]) {
    float2 aL = affld(affp, k0);
    float2 aR = affld(affp, k0 + (HASC ? 2 : 1));
    float2 aC = HASC ? affld(affp, k0 + 1) : make_float2(0.f, 0.f);
    #pragma unroll
    for (int c = 0; c < NCH; c++) {
        const float* r = mbase + c * PHW + dyoff;
        float2 vL, vC, vR;
        if (WIN) {
            float2 a = *(const float2*)(r - 2);
            float2 b = *(const float2*)(r);
            float2 e = *(const float2*)(r + 2);
            if (D == 1) {
                vL = make_float2(a.y, b.x);
                vR = make_float2(b.y, e.x);
            } else {
                vL = a;
                vR = e;
            }
            vC = b;
        } else {
            vL = *(const float2*)(r - D);
            vC = HASC ? *(const float2*)(r) : make_float2(0.f, 0.f);
            vR = *(const float2*)(r + D);
        }
        acc[c][0] = fmaf(aL.x, vL.x, acc[c][0]);
        acc[c][1] = fmaf(aL.y, vL.y, acc[c][1]);
        if (HASC) {
            acc[c][0] = fmaf(aC.x, vC.x, acc[c][0]);
            acc[c][1] = fmaf(aC.y, vC.y, acc[c][1]);
        }
        acc[c][0] = fmaf(aR.x, vR.x, acc[c][0]);
        acc[c][1] = fmaf(aR.y, vR.y, acc[c][1]);
    }
}

// Fused center rows of d=1 (k3 left, k4 right) and d=2 (k11 left, k12 right):
// all four taps live in the same 6-float window of row y -> load a,b,e once.
__device__ __forceinline__ void proc_center12(const float* __restrict__ mbase,
                                              const __half* __restrict__ affp,
                                              float acc[NCH][2]) {
    float2 a3  = affld(affp, 3);
    float2 a4  = affld(affp, 4);
    float2 a11 = affld(affp, 11);
    float2 a12 = affld(affp, 12);
    #pragma unroll
    for (int c = 0; c < NCH; c++) {
        const float* r = mbase + c * PHW;
        float2 a = *(const float2*)(r - 2);
        float2 b = *(const float2*)(r);
        float2 e = *(const float2*)(r + 2);
        // d=1: vL=(x-1,x)= (a.y,b.x), vR=(x+1,x+2)=(b.y,e.x)
        acc[c][0] = fmaf(a3.x, a.y, acc[c][0]);
        acc[c][1] = fmaf(a3.y, b.x, acc[c][1]);
        acc[c][0] = fmaf(a4.x, b.y, acc[c][0]);
        acc[c][1] = fmaf(a4.y, e.x, acc[c][1]);
        // d=2: vL=a, vR=e
        acc[c][0] = fmaf(a11.x, a.x, acc[c][0]);
        acc[c][1] = fmaf(a11.y, a.y, acc[c][1]);
        acc[c][0] = fmaf(a12.x, e.x, acc[c][0]);
        acc[c][1] = fmaf(a12.y, e.y, acc[c][1]);
    }
}

// block (112,2), grid (1,112,7): thread = 2 consecutive x-pixels, 3 channels.
__global__ __launch_bounds__(224) void iter_kernel(const float* __restrict__ src,
                                                   float* __restrict__ dst,
                                                   int pad_out) {
    const int x2 = threadIdx.x * 2;
    const int y  = blockIdx.y * 2 + threadIdx.y;
    const int p  = y * W + x2;
    const int pp = (y + PAD) * PW + (x2 + PAD);
    const int c0 = blockIdx.z * NCH;

    const float* __restrict__ mbase = src + (size_t)c0 * PHW + pp;
    const __half* __restrict__ affp = g_aff + p;

    float acc[NCH][2];
    #pragma unroll
    for (int c = 0; c < NCH; c++) { acc[c][0] = 0.f; acc[c][1] = 0.f; }

    proc_row<1,  true,  true >(mbase, -1*PW,  0, affp, acc);
    proc_row<1,  true,  true >(mbase, +1*PW,  5, affp, acc);
    proc_row<2,  true,  true >(mbase, -2*PW,  8, affp, acc);
    proc_row<2,  true,  true >(mbase, +2*PW, 13, affp, acc);
    proc_center12(mbase, affp, acc);
    proc_row<4,  false, true >(mbase, -4*PW, 16, affp, acc);
    proc_row<4,  false, false>(mbase,  0,    19, affp, acc);
    proc_row<4,  false, true >(mbase, +4*PW, 21, affp, acc);
    proc_row<8,  false, true >(mbase, -8*PW, 24, affp, acc);
    proc_row<8,  false, false>(mbase,  0,    27, affp, acc);
    proc_row<8,  false, true >(mbase, +8*PW, 29, affp, acc);
    proc_row<12, false, true >(mbase, -12*PW, 32, affp, acc);
    proc_row<12, false, false>(mbase,  0,     35, affp, acc);
    proc_row<12, false, true >(mbase, +12*PW, 37, affp, acc);
    proc_row<24, false, true >(mbase, -24*PW, 40, affp, acc);
    proc_row<24, false, false>(mbase,  0,     43, affp, acc);
    proc_row<24, false, true >(mbase, +24*PW, 45, affp, acc);

    if (pad_out) {
        #pragma unroll
        for (int c = 0; c < NCH; c++)
            *(float2*)(dst + (size_t)(c0+c)*PHW + pp) = make_float2(acc[c][0], acc[c][1]);
    } else {
        #pragma unroll
        for (int c = 0; c < NCH; c++)
            *(float2*)(dst + (size_t)(c0+c)*HW + p) = make_float2(acc[c][0], acc[c][1]);
    }
}

// ---------------- border-only replicate-pad refresh (float4 stripes) ----------
#define TB_N  (C*48*68)
#define SD_N  (C*224*12)
__global__ void padb_kernel(float* __restrict__ buf) {
    int idx = blockIdx.x * blockDim.x + threadIdx.x;
    if (idx < TB_N) {
        int c = idx / (48*68);
        int i = idx - c * (48*68);
        int r = i / 68, q4 = (i - r*68) * 4;
        int py = (r < 24) ? r : (r + 224);
        int y = clampi(py - PAD, 0, H-1);
        float4 v;
        v.x = buf[c*PHW + (y+PAD)*PW + clampi(q4+0-PAD, 0, W-1) + PAD];
        v.y = buf[c*PHW + (y+PAD)*PW + clampi(q4+1-PAD, 0, W-1) + PAD];
        v.z = buf[c*PHW + (y+PAD)*PW + clampi(q4+2-PAD, 0, W-1) + PAD];
        v.w = buf[c*PHW + (y+PAD)*PW + clampi(q4+3-PAD, 0, W-1) + PAD];
        *(float4*)(buf + c*PHW + py*PW + q4) = v;
        return;
    }
    idx -= TB_N;
    if (idx < SD_N) {
        int c = idx / (224*12);
        int i = idx - c * (224*12);
        int row = i / 12, s = i - row*12;
        int py = PAD + row;
        int q4 = (s < 6) ? s*4 : (PAD + W + (s-6)*4);
        float edge = (s < 6) ? buf[c*PHW + py*PW + PAD]
                             : buf[c*PHW + py*PW + PAD + W - 1];
        *(float4*)(buf + c*PHW + py*PW + q4) = make_float4(edge, edge, edge, edge);
    }
}

// ---------------- host pos softmax --------------------------------------------
static PosArr make_pos_host() {
    const float s2 = sqrtf(2.0f);
    const float base[8] = {s2, 1.f, s2, 1.f, 1.f, s2, 1.f, s2};
    const int DD[6] = {1, 2, 4, 8, 12, 24};
    float pos[K];
    float sum = 0.f;
    for (int di = 0; di < 6; di++)
        for (int o = 0; o < 8; o++) {
            float v = base[o] * (float)DD[di];
            pos[di*8+o] = v; sum += v;
        }
    float mean = sum / 48.f, ss = 0.f;
    for (int k = 0; k < K; k++) { float d = pos[k] - mean; ss += d * d; }
    float sd = sqrtf(ss / 47.f);
    float mx = -1e30f;
    for (int k = 0; k < K; k++) {
        float t = pos[k] / ((sd + EPSF) * W1F);
        pos[k] = -t * t;
        if (pos[k] > mx) mx = pos[k];
    }
    float es = 0.f;
    for (int k = 0; k < K; k++) { pos[k] = expf(pos[k] - mx); es += pos[k]; }
    PosArr out;
    for (int k = 0; k < K; k++) out.v[k] = pos[k] / es;
    return out;
}

// ---------------- launch ------------------------------------------------------
extern "C" void kernel_launch(void* const* d_in, const int* in_sizes, int n_in,
                              void* d_out, int out_size) {
    const float* imgs  = (const float*)d_in[0];
    const float* masks = (const float*)d_in[1];
    if (n_in >= 2 && in_sizes[0] == C*MH*MW) {
        const float* t = imgs; imgs = masks; masks = t;
    }
    float *buf0, *buf1;
    cudaGetSymbolAddress((void**)&buf0, g_pad0);
    cudaGetSymbolAddress((void**)&buf1, g_pad1);

    PosArr pos = make_pos_host();

    const int PREP_N = C*PHW + 3*PHW + 3*HW2;
    prep_kernel<<<(PREP_N + 255)/256, 256>>>(imgs, masks);
    aff2_kernel<<<(HW2 + 31)/32, 32>>>();
    aff1up_kernel<<<dim3(7, 56), dim3(32, 4)>>>(pos);

    const float* src = buf0;
    for (int i = 0; i < 10; i++) {
        int last = (i == 9);
        float* dst = last ? (float*)d_out : ((i & 1) ? buf0 : buf1);
        iter_kernel<<<dim3(1, 112, 7), dim3(112, 2)>>>(src, dst, !last);
        if (!last) padb_kernel<<<(TB_N + SD_N + 255)/256, 256>>>(dst);
        src = dst;
    }
}

// round 17
// speedup vs baseline: 3.2790x; 1.0379x over previous
#include <cuda_runtime.h>
#include <cuda_fp16.h>
#include <math.h>

#define H    224
#define W    224
#define HW   (224*224)
#define C    21
#define K    48
#define H2   67
#define W2   67
#define HW2  (67*67)
#define MH   56
#define MW   56
#define PAD  24
#define PW   272
#define PHW  (272*272)
#define EPSF 1e-8f
#define W1F  0.3f

// ---------------- device scratch ----------------
__device__ __align__(16) __half g_pad0[C*PHW];   // fp16 ping-pong masks
__device__ __align__(16) __half g_pad1[C*PHW];
__device__ __align__(16) float  g_imgp[3*PHW];
__device__ __align__(16) __half g_aff [K*HW];    // K-MAJOR fp16: [k][p]
__device__ __align__(16) float  g_imgs2[3*HW2];
__device__ __align__(16) float  g_aff2p[HW2*K];  // pixel-major [p2][k]

struct PosArr { float v[K]; };

__device__ __forceinline__ int clampi(int v, int lo, int hi) {
    return v < lo ? lo : (v > hi ? hi : v);
}

// ---------------- fused prep: upmask->pad0(fp16), padimg, downimg -------------
__global__ void prep_kernel(const float* __restrict__ imgs,
                            const float* __restrict__ masks) {
    int idx = blockIdx.x * blockDim.x + threadIdx.x;
    if (idx < C*PHW) {
        int c = idx / PHW;
        int q = idx - c * PHW;
        int py = q / PW, px = q - py * PW;
        int y = clampi(py - PAD, 0, H-1);
        int x = clampi(px - PAD, 0, W-1);
        float fy = (float)y * (55.f / 223.f);
        int y0 = (int)fy; float wy = fy - (float)y0; int y1 = min(y0 + 1, 55);
        float fx = (float)x * (55.f / 223.f);
        int x0 = (int)fx; float wx = fx - (float)x0; int x1 = min(x0 + 1, 55);
        const float* mc = masks + c * MH * MW;
        float r0 = mc[y0*MW+x0] * (1.f - wy) + mc[y1*MW+x0] * wy;
        float r1 = mc[y0*MW+x1] * (1.f - wy) + mc[y1*MW+x1] * wy;
        g_pad0[idx] = __float2half_rn(r0 * (1.f - wx) + r1 * wx);
        return;
    }
    idx -= C*PHW;
    if (idx < 3*PHW) {
        int c = idx / PHW;
        int q = idx - c * PHW;
        int py = q / PW, px = q - py * PW;
        int y = clampi(py - PAD, 0, H-1);
        int x = clampi(px - PAD, 0, W-1);
        g_imgp[idx] = imgs[c*HW + y*W + x];
        return;
    }
    idx -= 3*PHW;
    if (idx < 3*HW2) {
        int c = idx / HW2;
        int p = idx - c * HW2;
        int y = p / W2, x = p - y * W2;
        float fy = (float)y * (223.f / 66.f);
        int y0 = (int)fy; float wy = fy - (float)y0; int y1 = min(y0 + 1, 223);
        float fx = (float)x * (223.f / 66.f);
        int x0 = (int)fx; float wx = fx - (float)x0; int x1 = min(x0 + 1, 223);
        const float* ic = imgs + c * HW;
        float r0 = ic[y0*W+x0] * (1.f - wy) + ic[y1*W+x0] * wy;
        float r1 = ic[y0*W+x1] * (1.f - wy) + ic[y1*W+x1] * wy;
        g_imgs2[idx] = r0 * (1.f - wx) + r1 * wx;
    }
}

#define NB_ADDR(o, DI) \
    ((o)==0 ? rm[DI]+cm[DI] : (o)==1 ? rm[DI]+x   : (o)==2 ? rm[DI]+cp[DI] : \
     (o)==3 ? r0v  +cm[DI] : (o)==4 ? r0v  +cp[DI] : \
     (o)==5 ? rp[DI]+cm[DI] : (o)==6 ? rp[DI]+x   :            rp[DI]+cp[DI])

// ---------------- low-res affinity, pixel-major out ---------------------------
__global__ __launch_bounds__(32) void aff2_kernel() {
    int p = blockIdx.x * blockDim.x + threadIdx.x;
    if (p >= HW2) return;
    int y = p / W2, x = p - y * W2;
    const int DDc[6] = {1, 2, 4, 8, 12, 24};
    int rm[6], rp[6], cm[6], cp[6];
    #pragma unroll
    for (int di = 0; di < 6; di++) {
        int d = DDc[di];
        rm[di] = max(y - d, 0) * W2;
        rp[di] = min(y + d, H2-1) * W2;
        cm[di] = max(x - d, 0);
        cp[di] = min(x + d, W2-1);
    }
    int r0v = y * W2;

    float t[K];
    #pragma unroll
    for (int k = 0; k < K; k++) t[k] = 0.f;

    for (int c = 0; c < 3; c++) {
        const float* __restrict__ im = g_imgs2 + c * HW2;
        float ctr = im[p];
        float sum = 0.f, ss = 0.f;
        #pragma unroll
        for (int di = 0; di < 6; di++) {
            #pragma unroll
            for (int o = 0; o < 8; o++) {
                float v = im[NB_ADDR(o, di)];
                sum += v; ss = fmaf(v, v, ss);
            }
        }
        float mean = sum * (1.f/48.f);
        float var  = fmaxf((ss - sum * mean) * (1.f/47.f), 0.f);
        float inv  = 1.f / (sqrtf(var) + EPSF);
        float inv2 = inv * inv;
        #pragma unroll
        for (int di = 0; di < 6; di++) {
            #pragma unroll
            for (int o = 0; o < 8; o++) {
                float d = im[NB_ADDR(o, di)] - ctr;
                t[di*8+o] = fmaf(d * d, inv2, t[di*8+o]);
            }
        }
    }
    #pragma unroll
    for (int k = 0; k < K; k++) g_aff2p[p*K + k] = -t[k] * (1.f/3.f);
}

// ------- fused: fullres affinity softmax + upsampled aff2 softmax + pos -------
__global__ __launch_bounds__(128) void aff1up_kernel(PosArr pos) {
    const int x = blockIdx.x * 32 + threadIdx.x;
    const int y = blockIdx.y * 4  + threadIdx.y;
    const int p = y * W + x;
    const int pp = (y + PAD) * PW + (x + PAD);

    const int DY[8] = {-1,-1,-1, 0, 0, 1, 1, 1};
    const int DX[8] = {-1, 0, 1,-1, 1,-1, 0, 1};
    const int DDc[6] = {1, 2, 4, 8, 12, 24};

    float t[K];
    #pragma unroll
    for (int k = 0; k < K; k++) t[k] = 0.f;

    #pragma unroll 1
    for (int c = 0; c < 3; c++) {
        const float* __restrict__ im = g_imgp + c * PHW + pp;
        float ctr = im[0];
        float sum = 0.f, ss = 0.f;
        #pragma unroll
        for (int di = 0; di < 6; di++) {
            #pragma unroll
            for (int o = 0; o < 8; o++) {
                float v = im[DY[o]*DDc[di]*PW + DX[o]*DDc[di]];
                sum += v; ss = fmaf(v, v, ss);
            }
        }
        float mean = sum * (1.f/48.f);
        float var  = fmaxf((ss - sum * mean) * (1.f/47.f), 0.f);
        float inv  = 1.f / ((sqrtf(var) + EPSF) * W1F);
        float inv2 = inv * inv;
        #pragma unroll
        for (int di = 0; di < 6; di++) {
            #pragma unroll
            for (int o = 0; o < 8; o++) {
                float d = im[DY[o]*DDc[di]*PW + DX[o]*DDc[di]] - ctr;
                t[di*8+o] = fmaf(d * d, inv2, t[di*8+o]);
            }
        }
    }
    {
        float mx = -1e30f;
        #pragma unroll
        for (int k = 0; k < K; k++) { t[k] = -t[k] * (1.f/3.f); mx = fmaxf(mx, t[k]); }
        float es = 0.f;
        #pragma unroll
        for (int k = 0; k < K; k++) { t[k] = __expf(t[k] - mx); es += t[k]; }
        float inv = 1.f / es;
        #pragma unroll
        for (int k = 0; k < K; k++) t[k] *= inv;
    }

    {
        float fy = (float)y * (66.f / 223.f);
        int iy = (int)fy; float wy = fy - (float)iy; int iy1 = min(iy + 1, 66);
        float fx = (float)x * (66.f / 223.f);
        int ix = (int)fx; float wx = fx - (float)ix; int ix1 = min(ix + 1, 66);
        float w00 = (1.f-wy)*(1.f-wx), w01 = (1.f-wy)*wx;
        float w10 = wy*(1.f-wx),       w11 = wy*wx;

        const float4* c00 = (const float4*)(g_aff2p + (size_t)(iy *W2+ix )*K);
        const float4* c01 = (const float4*)(g_aff2p + (size_t)(iy *W2+ix1)*K);
        const float4* c10 = (const float4*)(g_aff2p + (size_t)(iy1*W2+ix )*K);
        const float4* c11 = (const float4*)(g_aff2p + (size_t)(iy1*W2+ix1)*K);

        float mx = -1e30f;
        #pragma unroll
        for (int i = 0; i < 12; i++) {
            float4 q0 = c00[i], q1 = c01[i], q2 = c10[i], q3 = c11[i];
            mx = fmaxf(mx, q0.x*w00 + q1.x*w01 + q2.x*w10 + q3.x*w11);
            mx = fmaxf(mx, q0.y*w00 + q1.y*w01 + q2.y*w10 + q3.y*w11);
            mx = fmaxf(mx, q0.z*w00 + q1.z*w01 + q2.z*w10 + q3.z*w11);
            mx = fmaxf(mx, q0.w*w00 + q1.w*w01 + q2.w*w10 + q3.w*w11);
        }
        float es = 0.f;
        #pragma unroll
        for (int i = 0; i < 12; i++) {
            float4 q0 = c00[i], q1 = c01[i], q2 = c10[i], q3 = c11[i];
            es += __expf(q0.x*w00 + q1.x*w01 + q2.x*w10 + q3.x*w11 - mx);
            es += __expf(q0.y*w00 + q1.y*w01 + q2.y*w10 + q3.y*w11 - mx);
            es += __expf(q0.z*w00 + q1.z*w01 + q2.z*w10 + q3.z*w11 - mx);
            es += __expf(q0.w*w00 + q1.w*w01 + q2.w*w10 + q3.w*w11 - mx);
        }
        float inv = 1.f / es;
        #pragma unroll
        for (int i = 0; i < 12; i++) {
            float4 q0 = c00[i], q1 = c01[i], q2 = c10[i], q3 = c11[i];
            t[4*i+0] += __expf(q0.x*w00 + q1.x*w01 + q2.x*w10 + q3.x*w11 - mx) * inv + pos.v[4*i+0];
            t[4*i+1] += __expf(q0.y*w00 + q1.y*w01 + q2.y*w10 + q3.y*w11 - mx) * inv + pos.v[4*i+1];
            t[4*i+2] += __expf(q0.z*w00 + q1.z*w01 + q2.z*w10 + q3.z*w11 - mx) * inv + pos.v[4*i+2];
            t[4*i+3] += __expf(q0.w*w00 + q1.w*w01 + q2.w*w10 + q3.w*w11 - mx) * inv + pos.v[4*i+3];
        }
    }

    #pragma unroll
    for (int k = 0; k < K; k++) g_aff[(size_t)k*HW + p] = __float2half_rn(t[k]);
}

// ---------------- propagation iteration: 2 px/thread, 3 channels, half2 -------
#define NCH 3

__device__ __forceinline__ float2 affld(const __half* __restrict__ affp, int k) {
    return __half22float2(*(const __half2*)(affp + (size_t)k * HW));
}
__device__ __forceinline__ float2 mld(const __half* __restrict__ p) {
    return __half22float2(*(const __half2*)p);
}

template<int D, bool WIN, bool HASC>
__device__ __forceinline__ void proc_row(const __half* __restrict__ mbase, int dyoff,
                                         int k0, const __half* __restrict__ affp,
                                         float acc[NCH][2]) {
    float2 aL = affld(affp, k0);
    float2 aR = affld(affp, k0 + (HASC ? 2 : 1));
    float2 aC = HASC ? affld(affp, k0 + 1) : make_float2(0.f, 0.f);
    #pragma unroll
    for (int c = 0; c < NCH; c++) {
        const __half* r = mbase + c * PHW + dyoff;
        float2 vL, vC, vR;
        if (WIN) {
            float2 a = mld(r - 2);
            float2 b = mld(r);
            float2 e = mld(r + 2);
            if (D == 1) {
                vL = make_float2(a.y, b.x);
                vR = make_float2(b.y, e.x);
            } else {
                vL = a;
                vR = e;
            }
            vC = b;
        } else {
            vL = mld(r - D);
            vC = HASC ? mld(r) : make_float2(0.f, 0.f);
            vR = mld(r + D);
        }
        acc[c][0] = fmaf(aL.x, vL.x, acc[c][0]);
        acc[c][1] = fmaf(aL.y, vL.y, acc[c][1]);
        if (HASC) {
            acc[c][0] = fmaf(aC.x, vC.x, acc[c][0]);
            acc[c][1] = fmaf(aC.y, vC.y, acc[c][1]);
        }
        acc[c][0] = fmaf(aR.x, vR.x, acc[c][0]);
        acc[c][1] = fmaf(aR.y, vR.y, acc[c][1]);
    }
}

// Fused center rows of d=1 and d=2 (shared 6-px window of row y).
__device__ __forceinline__ void proc_center12(const __half* __restrict__ mbase,
                                              const __half* __restrict__ affp,
                                              float acc[NCH][2]) {
    float2 a3  = affld(affp, 3);
    float2 a4  = affld(affp, 4);
    float2 a11 = affld(affp, 11);
    float2 a12 = affld(affp, 12);
    #pragma unroll
    for (int c = 0; c < NCH; c++) {
        const __half* r = mbase + c * PHW;
        float2 a = mld(r - 2);
        float2 b = mld(r);
        float2 e = mld(r + 2);
        acc[c][0] = fmaf(a3.x, a.y, acc[c][0]);
        acc[c][1] = fmaf(a3.y, b.x, acc[c][1]);
        acc[c][0] = fmaf(a4.x, b.y, acc[c][0]);
        acc[c][1] = fmaf(a4.y, e.x, acc[c][1]);
        acc[c][0] = fmaf(a11.x, a.x, acc[c][0]);
        acc[c][1] = fmaf(a11.y, a.y, acc[c][1]);
        acc[c][0] = fmaf(a12.x, e.x, acc[c][0]);
        acc[c][1] = fmaf(a12.y, e.y, acc[c][1]);
    }
}

// block (112,2), grid (1,112,7): thread = 2 consecutive x-pixels, 3 channels.
// pad_out: write fp16 padded dst; else write fp32 to fout (final output).
__global__ __launch_bounds__(224) void iter_kernel(const __half* __restrict__ src,
                                                   __half* __restrict__ dst,
                                                   float* __restrict__ fout,
                                                   int pad_out) {
    const int x2 = threadIdx.x * 2;
    const int y  = blockIdx.y * 2 + threadIdx.y;
    const int p  = y * W + x2;
    const int pp = (y + PAD) * PW + (x2 + PAD);
    const int c0 = blockIdx.z * NCH;

    const __half* __restrict__ mbase = src + (size_t)c0 * PHW + pp;
    const __half* __restrict__ affp  = g_aff + p;

    float acc[NCH][2];
    #pragma unroll
    for (int c = 0; c < NCH; c++) { acc[c][0] = 0.f; acc[c][1] = 0.f; }

    proc_row<1,  true,  true >(mbase, -1*PW,  0, affp, acc);
    proc_row<1,  true,  true >(mbase, +1*PW,  5, affp, acc);
    proc_row<2,  true,  true >(mbase, -2*PW,  8, affp, acc);
    proc_row<2,  true,  true >(mbase, +2*PW, 13, affp, acc);
    proc_center12(mbase, affp, acc);
    proc_row<4,  false, true >(mbase, -4*PW, 16, affp, acc);
    proc_row<4,  false, false>(mbase,  0,    19, affp, acc);
    proc_row<4,  false, true >(mbase, +4*PW, 21, affp, acc);
    proc_row<8,  false, true >(mbase, -8*PW, 24, affp, acc);
    proc_row<8,  false, false>(mbase,  0,    27, affp, acc);
    proc_row<8,  false, true >(mbase, +8*PW, 29, affp, acc);
    proc_row<12, false, true >(mbase, -12*PW, 32, affp, acc);
    proc_row<12, false, false>(mbase,  0,     35, affp, acc);
    proc_row<12, false, true >(mbase, +12*PW, 37, affp, acc);
    proc_row<24, false, true >(mbase, -24*PW, 40, affp, acc);
    proc_row<24, false, false>(mbase,  0,     43, affp, acc);
    proc_row<24, false, true >(mbase, +24*PW, 45, affp, acc);

    if (pad_out) {
        #pragma unroll
        for (int c = 0; c < NCH; c++)
            *(__half2*)(dst + (size_t)(c0+c)*PHW + pp) =
                __floats2half2_rn(acc[c][0], acc[c][1]);
    } else {
        #pragma unroll
        for (int c = 0; c < NCH; c++)
            *(float2*)(fout + (size_t)(c0+c)*HW + p) = make_float2(acc[c][0], acc[c][1]);
    }
}

// ---------------- border-only replicate-pad refresh (half2 stripes) -----------
#define TB_N  (C*48*136)
#define SD_N  (C*224*24)
__global__ void padb_kernel(__half* __restrict__ buf) {
    int idx = blockIdx.x * blockDim.x + threadIdx.x;
    if (idx < TB_N) {
        int c = idx / (48*136);
        int i = idx - c * (48*136);
        int r = i / 136, q2 = (i - r*136) * 2;
        int py = (r < 24) ? r : (r + 224);
        int y = clampi(py - PAD, 0, H-1);
        __half v0 = buf[c*PHW + (y+PAD)*PW + clampi(q2+0-PAD, 0, W-1) + PAD];
        __half v1 = buf[c*PHW + (y+PAD)*PW + clampi(q2+1-PAD, 0, W-1) + PAD];
        *(__half2*)(buf + c*PHW + py*PW + q2) = __halves2half2(v0, v1);
        return;
    }
    idx -= TB_N;
    if (idx < SD_N) {
        int c = idx / (224*24);
        int i = idx - c * (224*24);
        int row = i / 24, s = i - row*24;
        int py = PAD + row;
        int q2 = (s < 12) ? s*2 : (PAD + W + (s-12)*2);
        __half edge = (s < 12) ? buf[c*PHW + py*PW + PAD]
                               : buf[c*PHW + py*PW + PAD + W - 1];
        *(__half2*)(buf + c*PHW + py*PW + q2) = __halves2half2(edge, edge);
    }
}

// ---------------- host pos softmax --------------------------------------------
static PosArr make_pos_host() {
    const float s2 = sqrtf(2.0f);
    const float base[8] = {s2, 1.f, s2, 1.f, 1.f, s2, 1.f, s2};
    const int DD[6] = {1, 2, 4, 8, 12, 24};
    float pos[K];
    float sum = 0.f;
    for (int di = 0; di < 6; di++)
        for (int o = 0; o < 8; o++) {
            float v = base[o] * (float)DD[di];
            pos[di*8+o] = v; sum += v;
        }
    float mean = sum / 48.f, ss = 0.f;
    for (int k = 0; k < K; k++) { float d = pos[k] - mean; ss += d * d; }
    float sd = sqrtf(ss / 47.f);
    float mx = -1e30f;
    for (int k = 0; k < K; k++) {
        float t = pos[k] / ((sd + EPSF) * W1F);
        pos[k] = -t * t;
        if (pos[k] > mx) mx = pos[k];
    }
    float es = 0.f;
    for (int k = 0; k < K; k++) { pos[k] = expf(pos[k] - mx); es += pos[k]; }
    PosArr out;
    for (int k = 0; k < K; k++) out.v[k] = pos[k] / es;
    return out;
}

// ---------------- launch ------------------------------------------------------
extern "C" void kernel_launch(void* const* d_in, const int* in_sizes, int n_in,
                              void* d_out, int out_size) {
    const float* imgs  = (const float*)d_in[0];
    const float* masks = (const float*)d_in[1];
    if (n_in >= 2 && in_sizes[0] == C*MH*MW) {
        const float* t = imgs; imgs = masks; masks = t;
    }
    __half *buf0, *buf1;
    cudaGetSymbolAddress((void**)&buf0, g_pad0);
    cudaGetSymbolAddress((void**)&buf1, g_pad1);

    PosArr pos = make_pos_host();

    const int PREP_N = C*PHW + 3*PHW + 3*HW2;
    prep_kernel<<<(PREP_N + 255)/256, 256>>>(imgs, masks);
    aff2_kernel<<<(HW2 + 31)/32, 32>>>();
    aff1up_kernel<<<dim3(7, 56), dim3(32, 4)>>>(pos);

    const __half* src = buf0;
    for (int i = 0; i < 10; i++) {
        int last = (i == 9);
        __half* dst = (i & 1) ? buf0 : buf1;
        iter_kernel<<<dim3(1, 112, 7), dim3(112, 2)>>>(src, dst, (float*)d_out, !last);
        if (!last) {
            padb_kernel<<<(TB_N + SD_N + 255)/256, 256>>>(dst);
            src = dst;
        }
    }
}